// round 4
// baseline (speedup 1.0000x reference)
#include <cuda_runtime.h>
#include <math.h>

// Problem constants
#define DMODEL 1024
#define MTOK   8192      // B*S
#define FFDIM  4096
#define NHEAD  16
#define HDIM   64
#define SEQ    1024
#define BATCH  8

// ---------------- scratch (device globals; referenced directly in kernels) ------
// b0: h (LN out) then ctx        b1: q then x2        b2: k        b3: v
// b4: FFN intermediate
__device__ float g_b0[MTOK * DMODEL];
__device__ float g_b1[MTOK * DMODEL];
__device__ float g_b2[MTOK * DMODEL];
__device__ float g_b3[MTOK * DMODEL];
__device__ float g_b4[MTOK * FFDIM];

template <int ID> __device__ __forceinline__ float* buf() {
    if constexpr (ID == 0) return g_b0;
    else if constexpr (ID == 1) return g_b1;
    else if constexpr (ID == 2) return g_b2;
    else if constexpr (ID == 3) return g_b3;
    else return g_b4;
}

// ---------------- LayerNorm: one block per row (1024 cols, 256 thr x 4) ----------
// SRCID = -1 -> use external src pointer; DSTID selects scratch buffer.
template <int SRCID, int DSTID>
__global__ __launch_bounds__(256) void ln_kernel(const float* __restrict__ xext,
                                                 const float* __restrict__ g,
                                                 const float* __restrict__ be) {
    const float* src = (SRCID < 0) ? xext : buf<(SRCID < 0) ? 0 : SRCID>();
    float* dst = buf<DSTID>();
    __shared__ float s1[256], s2[256];
    const int row = blockIdx.x;
    const int tid = threadIdx.x;
    const float4 v = ((const float4*)(src + (size_t)row * DMODEL))[tid];
    float sum = v.x + v.y + v.z + v.w;
    float sq  = v.x*v.x + v.y*v.y + v.z*v.z + v.w*v.w;
    s1[tid] = sum; s2[tid] = sq;
    __syncthreads();
    for (int s = 128; s > 0; s >>= 1) {
        if (tid < s) { s1[tid] += s1[tid + s]; s2[tid] += s2[tid + s]; }
        __syncthreads();
    }
    const float mean = s1[0] * (1.0f / DMODEL);
    const float var  = s2[0] * (1.0f / DMODEL) - mean * mean;
    const float rs   = rsqrtf(var + 1e-5f);
    const float4 gv = ((const float4*)g)[tid];
    const float4 bv = ((const float4*)be)[tid];
    float4 o;
    o.x = (v.x - mean) * rs * gv.x + bv.x;
    o.y = (v.y - mean) * rs * gv.y + bv.y;
    o.z = (v.z - mean) * rs * gv.z + bv.z;
    o.w = (v.w - mean) * rs * gv.w + bv.w;
    ((float4*)(dst + (size_t)row * DMODEL))[tid] = o;
}

// ---------------- Dense GEMM: C = A @ W + bias (+GELU) (+residual) ---------------
// 128x128 block tile, BK=16, 256 threads, 8x8 per thread.
// SRCID: scratch buffer for A. DSTID: -1 -> external out pointer, else buffer.
// ACT: 1 = exact GELU. RES: -1 none, -2 external res pointer, else buffer id.
template <int SRCID, int DSTID, int ACT, int RES>
__global__ __launch_bounds__(256) void gemm_kernel(const float* __restrict__ W,
                                                   const float* __restrict__ bias,
                                                   float* __restrict__ extC,
                                                   const float* __restrict__ extRes,
                                                   int N, int K) {
    const float* A = buf<SRCID>();
    float* C = (DSTID < 0) ? extC : buf<(DSTID < 0) ? 0 : DSTID>();
    const float* R = (RES == -1) ? nullptr
                   : (RES == -2) ? extRes : buf<(RES < 0) ? 0 : RES>();

    __shared__ float As[16][132];   // [k][m]
    __shared__ float Bs[16][128];   // [k][n]
    const int tid = threadIdx.x;
    const int tx  = tid & 15;
    const int ty  = tid >> 4;
    const int rowBase = blockIdx.y * 128;
    const int colBase = blockIdx.x * 128;

    float acc[8][8];
#pragma unroll
    for (int i = 0; i < 8; i++)
#pragma unroll
        for (int j = 0; j < 8; j++) acc[i][j] = 0.0f;

    for (int k0 = 0; k0 < K; k0 += 16) {
#pragma unroll
        for (int t = 0; t < 2; t++) {
            const int i  = t * 256 + tid;          // 0..511
            const int ar = i >> 2, ac = (i & 3) << 2;
            const float4 av = *(const float4*)(A + (size_t)(rowBase + ar) * K + k0 + ac);
            As[ac + 0][ar] = av.x; As[ac + 1][ar] = av.y;
            As[ac + 2][ar] = av.z; As[ac + 3][ar] = av.w;
            const int br = i >> 5, bc = (i & 31) << 2;
            *(float4*)&Bs[br][bc] = *(const float4*)(W + (size_t)(k0 + br) * N + colBase + bc);
        }
        __syncthreads();
#pragma unroll
        for (int kk = 0; kk < 16; kk++) {
            float ra[8], rb[8];
            *(float4*)(ra)     = *(float4*)&As[kk][ty * 8];
            *(float4*)(ra + 4) = *(float4*)&As[kk][ty * 8 + 4];
            *(float4*)(rb)     = *(float4*)&Bs[kk][tx * 8];
            *(float4*)(rb + 4) = *(float4*)&Bs[kk][tx * 8 + 4];
#pragma unroll
            for (int i = 0; i < 8; i++)
#pragma unroll
                for (int j = 0; j < 8; j++)
                    acc[i][j] = fmaf(ra[i], rb[j], acc[i][j]);
        }
        __syncthreads();
    }

#pragma unroll
    for (int i = 0; i < 8; i++) {
        const int row = rowBase + ty * 8 + i;
#pragma unroll
        for (int j = 0; j < 8; j++) {
            const int col = colBase + tx * 8 + j;
            float vv = acc[i][j] + bias[col];
            if (ACT == 1) vv = 0.5f * vv * (1.0f + erff(vv * 0.70710678118654752f));
            if (R != nullptr) vv += R[(size_t)row * N + col];
            C[(size_t)row * N + col] = vv;
        }
    }
}

// ---------------- Fused flash attention ------------------------------------------
// Reads q=b1, k=b2, v=b3; writes ctx=b0. One block per (bh, 64-row q-tile).
// 256 threads in 16x16; each thread owns a 4x4 slice. Online softmax, 16 k-tiles.
__global__ __launch_bounds__(256) void fa_kernel() {
    const float* q = g_b1;
    const float* k = g_b2;
    const float* v = g_b3;
    float* ctx = g_b0;

    __shared__ float Qs[64][68];
    __shared__ float Ks[64][68];
    __shared__ float Vs[64][68];
    __shared__ float Ps[64][68];

    const int bh = blockIdx.y;
    const int b  = bh >> 4, h = bh & 15;
    const int qBase = blockIdx.x * 64;
    const float* qb = q + ((size_t)b * SEQ + qBase) * DMODEL + h * HDIM;
    const float* kb = k + ((size_t)b * SEQ) * DMODEL + h * HDIM;
    const float* vb = v + ((size_t)b * SEQ) * DMODEL + h * HDIM;

    const int tid = threadIdx.x;
    const int tx  = tid & 15;
    const int ty  = tid >> 4;

#pragma unroll
    for (int t = 0; t < 4; t++) {
        const int i = t * 256 + tid;              // 0..1023 float4s
        const int r = i >> 4, c = (i & 15) << 2;
        const float4 qv = *(const float4*)(qb + (size_t)r * DMODEL + c);
        Qs[r][c] = qv.x; Qs[r][c+1] = qv.y; Qs[r][c+2] = qv.z; Qs[r][c+3] = qv.w;
    }

    float m[4], l[4], acc[4][4];
#pragma unroll
    for (int i = 0; i < 4; i++) {
        m[i] = -INFINITY; l[i] = 0.0f;
#pragma unroll
        for (int j = 0; j < 4; j++) acc[i][j] = 0.0f;
    }

    for (int kt = 0; kt < SEQ / 64; kt++) {
        __syncthreads();   // previous PV done before overwriting Ks/Vs
        const float* kbt = kb + (size_t)kt * 64 * DMODEL;
        const float* vbt = vb + (size_t)kt * 64 * DMODEL;
#pragma unroll
        for (int t = 0; t < 4; t++) {
            const int i = t * 256 + tid;
            const int r = i >> 4, c = (i & 15) << 2;
            const float4 kv = *(const float4*)(kbt + (size_t)r * DMODEL + c);
            Ks[r][c] = kv.x; Ks[r][c+1] = kv.y; Ks[r][c+2] = kv.z; Ks[r][c+3] = kv.w;
            const float4 vv = *(const float4*)(vbt + (size_t)r * DMODEL + c);
            Vs[r][c] = vv.x; Vs[r][c+1] = vv.y; Vs[r][c+2] = vv.z; Vs[r][c+3] = vv.w;
        }
        __syncthreads();

        // S = Q K^T / 8 (per-thread 4x4)
        float s[4][4];
#pragma unroll
        for (int i = 0; i < 4; i++)
#pragma unroll
            for (int j = 0; j < 4; j++) s[i][j] = 0.0f;
#pragma unroll 8
        for (int kk = 0; kk < 64; kk++) {
            float ra[4], rb[4];
#pragma unroll
            for (int i = 0; i < 4; i++) ra[i] = Qs[ty * 4 + i][kk];
#pragma unroll
            for (int j = 0; j < 4; j++) rb[j] = Ks[tx * 4 + j][kk];
#pragma unroll
            for (int i = 0; i < 4; i++)
#pragma unroll
                for (int j = 0; j < 4; j++)
                    s[i][j] = fmaf(ra[i], rb[j], s[i][j]);
        }

        // online softmax (16 threads with same ty share a row-group; they sit in
        // lanes ty*16..ty*16+15 of two warps -> xor-shuffle width 16 is safe)
#pragma unroll
        for (int i = 0; i < 4; i++) {
            float mr = -INFINITY;
#pragma unroll
            for (int j = 0; j < 4; j++) { s[i][j] *= 0.125f; mr = fmaxf(mr, s[i][j]); }
#pragma unroll
            for (int off = 8; off > 0; off >>= 1)
                mr = fmaxf(mr, __shfl_xor_sync(0xffffffffu, mr, off));
            const float mn = fmaxf(m[i], mr);
            const float alpha = __expf(m[i] - mn);
            m[i] = mn;
            float ls = 0.0f;
#pragma unroll
            for (int j = 0; j < 4; j++) {
                const float p = __expf(s[i][j] - mn);
                s[i][j] = p;
                ls += p;
            }
#pragma unroll
            for (int off = 8; off > 0; off >>= 1)
                ls += __shfl_xor_sync(0xffffffffu, ls, off);
            l[i] = l[i] * alpha + ls;
#pragma unroll
            for (int j = 0; j < 4; j++) acc[i][j] *= alpha;
#pragma unroll
            for (int j = 0; j < 4; j++) Ps[ty * 4 + i][tx * 4 + j] = s[i][j];
        }
        __syncthreads();

        // acc += P @ V
#pragma unroll 8
        for (int j = 0; j < 64; j++) {
            float ra[4], rb[4];
#pragma unroll
            for (int i = 0; i < 4; i++) ra[i] = Ps[ty * 4 + i][j];
            *(float4*)rb = *(float4*)&Vs[j][tx * 4];
#pragma unroll
            for (int i = 0; i < 4; i++)
#pragma unroll
                for (int d = 0; d < 4; d++)
                    acc[i][d] = fmaf(ra[i], rb[d], acc[i][d]);
        }
    }

    // write ctx[b, q, h, :] = acc / l
#pragma unroll
    for (int i = 0; i < 4; i++) {
        const float inv = 1.0f / l[i];
        const int qr = qBase + ty * 4 + i;
        float4 o;
        o.x = acc[i][0] * inv; o.y = acc[i][1] * inv;
        o.z = acc[i][2] * inv; o.w = acc[i][3] * inv;
        *(float4*)(ctx + ((size_t)b * SEQ + qr) * DMODEL + h * HDIM + tx * 4) = o;
    }
}

// ---------------- launcher: kernel launches ONLY ---------------------------------
extern "C" void kernel_launch(void* const* d_in, const int* in_sizes, int n_in,
                              void* d_out, int out_size) {
    const float* x   = (const float*)d_in[0];
    const float* Wq  = (const float*)d_in[1];
    const float* bq  = (const float*)d_in[2];
    const float* Wk  = (const float*)d_in[3];
    const float* bk  = (const float*)d_in[4];
    const float* Wv  = (const float*)d_in[5];
    const float* bv  = (const float*)d_in[6];
    const float* Wo  = (const float*)d_in[7];
    const float* bo  = (const float*)d_in[8];
    const float* W1  = (const float*)d_in[9];
    const float* b1  = (const float*)d_in[10];
    const float* W2  = (const float*)d_in[11];
    const float* b2  = (const float*)d_in[12];
    const float* g1  = (const float*)d_in[13];
    const float* be1 = (const float*)d_in[14];
    const float* g2  = (const float*)d_in[15];
    const float* be2 = (const float*)d_in[16];
    float* out = (float*)d_out;

    const dim3 gD(DMODEL / 128, MTOK / 128);   // 8 x 64
    const dim3 gF(FFDIM / 128, MTOK / 128);    // 32 x 64

    // --- attention block ---
    ln_kernel<-1, 0><<<MTOK, 256>>>(x, g1, be1);                       // h=b0
    gemm_kernel<0, 1, 0, -1><<<gD, 256>>>(Wq, bq, nullptr, nullptr, DMODEL, DMODEL); // q=b1
    gemm_kernel<0, 2, 0, -1><<<gD, 256>>>(Wk, bk, nullptr, nullptr, DMODEL, DMODEL); // k=b2
    gemm_kernel<0, 3, 0, -1><<<gD, 256>>>(Wv, bv, nullptr, nullptr, DMODEL, DMODEL); // v=b3
    fa_kernel<<<dim3(SEQ / 64, BATCH * NHEAD), 256>>>();               // ctx=b0
    gemm_kernel<0, 1, 0, -2><<<gD, 256>>>(Wo, bo, nullptr, x, DMODEL, DMODEL);       // x2=b1

    // --- FFN block ---
    ln_kernel<1, 0><<<MTOK, 256>>>(nullptr, g2, be2);                  // h=b0
    gemm_kernel<0, 4, 1, -1><<<gF, 256>>>(W1, b1, nullptr, nullptr, FFDIM, DMODEL);  // act=b4
    gemm_kernel<4, -1, 0, 1><<<gD, 256>>>(W2, b2, out, nullptr, DMODEL, FFDIM);      // out
}

// round 5
// speedup vs baseline: 1.2014x; 1.2014x over previous
#include <cuda_runtime.h>
#include <math.h>
#include <stdint.h>

// Problem constants
#define DMODEL 1024
#define MTOK   8192      // B*S
#define FFDIM  4096
#define NHEAD  16
#define HDIM   64
#define SEQ    1024
#define BATCH  8

// ---------------- scratch (device globals; referenced directly in kernels) ------
// b0: h (LN out) then ctx        b1: q then x2        b2: k        b3: v
// b4: FFN intermediate
__device__ float g_b0[MTOK * DMODEL];
__device__ float g_b1[MTOK * DMODEL];
__device__ float g_b2[MTOK * DMODEL];
__device__ float g_b3[MTOK * DMODEL];
__device__ float g_b4[MTOK * FFDIM];

template <int ID> __device__ __forceinline__ float* buf() {
    if constexpr (ID == 0) return g_b0;
    else if constexpr (ID == 1) return g_b1;
    else if constexpr (ID == 2) return g_b2;
    else if constexpr (ID == 3) return g_b3;
    else return g_b4;
}

// ---------------- tf32 mma helpers ----------------------------------------------
__device__ __forceinline__ uint32_t f2tf32(float x) {
    uint32_t r;
    asm("cvt.rna.tf32.f32 %0, %1;" : "=r"(r) : "f"(x));
    return r;
}

__device__ __forceinline__ void mma_tf32(float* d, const uint32_t* a, const uint32_t* b) {
    asm volatile(
        "mma.sync.aligned.m16n8k8.row.col.f32.tf32.tf32.f32 "
        "{%0,%1,%2,%3}, {%4,%5,%6,%7}, {%8,%9}, {%0,%1,%2,%3};"
        : "+f"(d[0]), "+f"(d[1]), "+f"(d[2]), "+f"(d[3])
        : "r"(a[0]), "r"(a[1]), "r"(a[2]), "r"(a[3]), "r"(b[0]), "r"(b[1]));
}

// ---------------- LayerNorm: one block per row (1024 cols, 256 thr x 4) ----------
template <int SRCID, int DSTID>
__global__ __launch_bounds__(256) void ln_kernel(const float* __restrict__ xext,
                                                 const float* __restrict__ g,
                                                 const float* __restrict__ be) {
    const float* src = (SRCID < 0) ? xext : buf<(SRCID < 0) ? 0 : SRCID>();
    float* dst = buf<DSTID>();
    __shared__ float s1[256], s2[256];
    const int row = blockIdx.x;
    const int tid = threadIdx.x;
    const float4 v = ((const float4*)(src + (size_t)row * DMODEL))[tid];
    float sum = v.x + v.y + v.z + v.w;
    float sq  = v.x*v.x + v.y*v.y + v.z*v.z + v.w*v.w;
    s1[tid] = sum; s2[tid] = sq;
    __syncthreads();
    for (int s = 128; s > 0; s >>= 1) {
        if (tid < s) { s1[tid] += s1[tid + s]; s2[tid] += s2[tid + s]; }
        __syncthreads();
    }
    const float mean = s1[0] * (1.0f / DMODEL);
    const float var  = s2[0] * (1.0f / DMODEL) - mean * mean;
    const float rs   = rsqrtf(var + 1e-5f);
    const float4 gv = ((const float4*)g)[tid];
    const float4 bv = ((const float4*)be)[tid];
    float4 o;
    o.x = (v.x - mean) * rs * gv.x + bv.x;
    o.y = (v.y - mean) * rs * gv.y + bv.y;
    o.z = (v.z - mean) * rs * gv.z + bv.z;
    o.w = (v.w - mean) * rs * gv.w + bv.w;
    ((float4*)(dst + (size_t)row * DMODEL))[tid] = o;
}

// ---------------- Dense GEMM on tensor cores (tf32) ------------------------------
// C = A[M,K] @ W[K,N] + bias (+GELU) (+residual).
// 128x128 block tile, BK=16, 256 threads = 8 warps in 2(m) x 4(n); warp tile 64x32.
// Fragments per warp: 4 m-frags (m16) x 4 n-frags (n8), k8 substeps.
// Smem: As row-major [128][20] (stride 20 -> conflict-free fragment loads),
//       Bs [16][136]  (stride 136 -> conflict-free fragment loads).
template <int SRCID, int DSTID, int ACT, int RES>
__global__ __launch_bounds__(256) void gemm_tc_kernel(const float* __restrict__ W,
                                                      const float* __restrict__ bias,
                                                      float* __restrict__ extC,
                                                      const float* __restrict__ extRes,
                                                      int N, int K) {
    const float* A = buf<SRCID>();
    float* C = (DSTID < 0) ? extC : buf<(DSTID < 0) ? 0 : DSTID>();
    const float* R = (RES == -1) ? nullptr
                   : (RES == -2) ? extRes : buf<(RES < 0) ? 0 : RES>();

    __shared__ uint32_t As[128 * 20];
    __shared__ uint32_t Bs[16 * 136];

    const int tid  = threadIdx.x;
    const int lane = tid & 31;
    const int wid  = tid >> 5;
    const int mw0  = (wid >> 2) * 64;   // warp m offset in tile
    const int nw0  = (wid & 3) * 32;    // warp n offset in tile
    const int lr   = lane >> 2;         // 0..7
    const int lc   = lane & 3;          // 0..3
    const int rowBase = blockIdx.y * 128;
    const int colBase = blockIdx.x * 128;

    float acc[4][4][4];
#pragma unroll
    for (int i = 0; i < 4; i++)
#pragma unroll
        for (int j = 0; j < 4; j++)
#pragma unroll
            for (int c = 0; c < 4; c++) acc[i][j][c] = 0.0f;

    for (int k0 = 0; k0 < K; k0 += 16) {
#pragma unroll
        for (int t = 0; t < 2; t++) {
            const int i  = t * 256 + tid;            // 0..511
            const int ar = i >> 2, ac = (i & 3) << 2;
            const float4 av = *(const float4*)(A + (size_t)(rowBase + ar) * K + k0 + ac);
            uint4 au;
            au.x = f2tf32(av.x); au.y = f2tf32(av.y);
            au.z = f2tf32(av.z); au.w = f2tf32(av.w);
            *(uint4*)&As[ar * 20 + ac] = au;
            const int br = i >> 5, bc = (i & 31) << 2;
            const float4 bv = *(const float4*)(W + (size_t)(k0 + br) * N + colBase + bc);
            uint4 bu;
            bu.x = f2tf32(bv.x); bu.y = f2tf32(bv.y);
            bu.z = f2tf32(bv.z); bu.w = f2tf32(bv.w);
            *(uint4*)&Bs[br * 136 + bc] = bu;
        }
        __syncthreads();

#pragma unroll
        for (int sub = 0; sub < 16; sub += 8) {
            uint32_t a[4][4];
#pragma unroll
            for (int i = 0; i < 4; i++) {
                const uint32_t* p = As + (mw0 + i * 16 + lr) * 20 + sub + lc;
                a[i][0] = p[0];
                a[i][1] = p[8 * 20];
                a[i][2] = p[4];
                a[i][3] = p[8 * 20 + 4];
            }
#pragma unroll
            for (int j = 0; j < 4; j++) {
                const uint32_t* p = Bs + (sub + lc) * 136 + nw0 + j * 8 + lr;
                uint32_t b[2];
                b[0] = p[0];
                b[1] = p[4 * 136];
#pragma unroll
                for (int i = 0; i < 4; i++) mma_tf32(acc[i][j], a[i][j == j ? 0 : 0] == a[i][0] ? a[i] : a[i], b);
            }
        }
        __syncthreads();
    }

    // epilogue: bias (+GELU) (+residual), float2 stores (cols c0,c0+1 contiguous)
#pragma unroll
    for (int i = 0; i < 4; i++) {
        const int r0 = rowBase + mw0 + i * 16 + lr;
#pragma unroll
        for (int j = 0; j < 4; j++) {
            const int c0 = colBase + nw0 + j * 8 + 2 * lc;
            const float b0v = bias[c0], b1v = bias[c0 + 1];
            float v00 = acc[i][j][0] + b0v;
            float v01 = acc[i][j][1] + b1v;
            float v10 = acc[i][j][2] + b0v;
            float v11 = acc[i][j][3] + b1v;
            if (ACT == 1) {
                v00 = 0.5f * v00 * (1.0f + erff(v00 * 0.70710678118654752f));
                v01 = 0.5f * v01 * (1.0f + erff(v01 * 0.70710678118654752f));
                v10 = 0.5f * v10 * (1.0f + erff(v10 * 0.70710678118654752f));
                v11 = 0.5f * v11 * (1.0f + erff(v11 * 0.70710678118654752f));
            }
            if (R != nullptr) {
                const float2 r0v = *(const float2*)(R + (size_t)r0 * N + c0);
                const float2 r1v = *(const float2*)(R + (size_t)(r0 + 8) * N + c0);
                v00 += r0v.x; v01 += r0v.y;
                v10 += r1v.x; v11 += r1v.y;
            }
            float2 o0; o0.x = v00; o0.y = v01;
            float2 o1; o1.x = v10; o1.y = v11;
            *(float2*)(C + (size_t)r0 * N + c0) = o0;
            *(float2*)(C + (size_t)(r0 + 8) * N + c0) = o1;
        }
    }
}

// ---------------- Fused flash attention (fp32 SIMT, unchanged) -------------------
__global__ __launch_bounds__(256) void fa_kernel() {
    const float* q = g_b1;
    const float* k = g_b2;
    const float* v = g_b3;
    float* ctx = g_b0;

    __shared__ float Qs[64][68];
    __shared__ float Ks[64][68];
    __shared__ float Vs[64][68];
    __shared__ float Ps[64][68];

    const int bh = blockIdx.y;
    const int b  = bh >> 4, h = bh & 15;
    const int qBase = blockIdx.x * 64;
    const float* qb = q + ((size_t)b * SEQ + qBase) * DMODEL + h * HDIM;
    const float* kb = k + ((size_t)b * SEQ) * DMODEL + h * HDIM;
    const float* vb = v + ((size_t)b * SEQ) * DMODEL + h * HDIM;

    const int tid = threadIdx.x;
    const int tx  = tid & 15;
    const int ty  = tid >> 4;

#pragma unroll
    for (int t = 0; t < 4; t++) {
        const int i = t * 256 + tid;
        const int r = i >> 4, c = (i & 15) << 2;
        const float4 qv = *(const float4*)(qb + (size_t)r * DMODEL + c);
        Qs[r][c] = qv.x; Qs[r][c+1] = qv.y; Qs[r][c+2] = qv.z; Qs[r][c+3] = qv.w;
    }

    float m[4], l[4], acc[4][4];
#pragma unroll
    for (int i = 0; i < 4; i++) {
        m[i] = -INFINITY; l[i] = 0.0f;
#pragma unroll
        for (int j = 0; j < 4; j++) acc[i][j] = 0.0f;
    }

    for (int kt = 0; kt < SEQ / 64; kt++) {
        __syncthreads();
        const float* kbt = kb + (size_t)kt * 64 * DMODEL;
        const float* vbt = vb + (size_t)kt * 64 * DMODEL;
#pragma unroll
        for (int t = 0; t < 4; t++) {
            const int i = t * 256 + tid;
            const int r = i >> 4, c = (i & 15) << 2;
            const float4 kv = *(const float4*)(kbt + (size_t)r * DMODEL + c);
            Ks[r][c] = kv.x; Ks[r][c+1] = kv.y; Ks[r][c+2] = kv.z; Ks[r][c+3] = kv.w;
            const float4 vv = *(const float4*)(vbt + (size_t)r * DMODEL + c);
            Vs[r][c] = vv.x; Vs[r][c+1] = vv.y; Vs[r][c+2] = vv.z; Vs[r][c+3] = vv.w;
        }
        __syncthreads();

        float s[4][4];
#pragma unroll
        for (int i = 0; i < 4; i++)
#pragma unroll
            for (int j = 0; j < 4; j++) s[i][j] = 0.0f;
#pragma unroll 8
        for (int kk = 0; kk < 64; kk++) {
            float ra[4], rb[4];
#pragma unroll
            for (int i = 0; i < 4; i++) ra[i] = Qs[ty * 4 + i][kk];
#pragma unroll
            for (int j = 0; j < 4; j++) rb[j] = Ks[tx * 4 + j][kk];
#pragma unroll
            for (int i = 0; i < 4; i++)
#pragma unroll
                for (int j = 0; j < 4; j++)
                    s[i][j] = fmaf(ra[i], rb[j], s[i][j]);
        }

#pragma unroll
        for (int i = 0; i < 4; i++) {
            float mr = -INFINITY;
#pragma unroll
            for (int j = 0; j < 4; j++) { s[i][j] *= 0.125f; mr = fmaxf(mr, s[i][j]); }
#pragma unroll
            for (int off = 8; off > 0; off >>= 1)
                mr = fmaxf(mr, __shfl_xor_sync(0xffffffffu, mr, off));
            const float mn = fmaxf(m[i], mr);
            const float alpha = __expf(m[i] - mn);
            m[i] = mn;
            float ls = 0.0f;
#pragma unroll
            for (int j = 0; j < 4; j++) {
                const float p = __expf(s[i][j] - mn);
                s[i][j] = p;
                ls += p;
            }
#pragma unroll
            for (int off = 8; off > 0; off >>= 1)
                ls += __shfl_xor_sync(0xffffffffu, ls, off);
            l[i] = l[i] * alpha + ls;
#pragma unroll
            for (int j = 0; j < 4; j++) acc[i][j] *= alpha;
#pragma unroll
            for (int j = 0; j < 4; j++) Ps[ty * 4 + i][tx * 4 + j] = s[i][j];
        }
        __syncthreads();

#pragma unroll 8
        for (int j = 0; j < 64; j++) {
            float ra[4], rb[4];
#pragma unroll
            for (int i = 0; i < 4; i++) ra[i] = Ps[ty * 4 + i][j];
            *(float4*)rb = *(float4*)&Vs[j][tx * 4];
#pragma unroll
            for (int i = 0; i < 4; i++)
#pragma unroll
                for (int d = 0; d < 4; d++)
                    acc[i][d] = fmaf(ra[i], rb[d], acc[i][d]);
        }
    }

#pragma unroll
    for (int i = 0; i < 4; i++) {
        const float inv = 1.0f / l[i];
        const int qr = qBase + ty * 4 + i;
        float4 o;
        o.x = acc[i][0] * inv; o.y = acc[i][1] * inv;
        o.z = acc[i][2] * inv; o.w = acc[i][3] * inv;
        *(float4*)(ctx + ((size_t)b * SEQ + qr) * DMODEL + h * HDIM + tx * 4) = o;
    }
}

// ---------------- launcher: kernel launches ONLY ---------------------------------
extern "C" void kernel_launch(void* const* d_in, const int* in_sizes, int n_in,
                              void* d_out, int out_size) {
    const float* x   = (const float*)d_in[0];
    const float* Wq  = (const float*)d_in[1];
    const float* bq  = (const float*)d_in[2];
    const float* Wk  = (const float*)d_in[3];
    const float* bk  = (const float*)d_in[4];
    const float* Wv  = (const float*)d_in[5];
    const float* bv  = (const float*)d_in[6];
    const float* Wo  = (const float*)d_in[7];
    const float* bo  = (const float*)d_in[8];
    const float* W1  = (const float*)d_in[9];
    const float* b1  = (const float*)d_in[10];
    const float* W2  = (const float*)d_in[11];
    const float* b2  = (const float*)d_in[12];
    const float* g1  = (const float*)d_in[13];
    const float* be1 = (const float*)d_in[14];
    const float* g2  = (const float*)d_in[15];
    const float* be2 = (const float*)d_in[16];
    float* out = (float*)d_out;

    const dim3 gD(DMODEL / 128, MTOK / 128);   // 8 x 64
    const dim3 gF(FFDIM / 128, MTOK / 128);    // 32 x 64

    // --- attention block ---
    ln_kernel<-1, 0><<<MTOK, 256>>>(x, g1, be1);                                        // h=b0
    gemm_tc_kernel<0, 1, 0, -1><<<gD, 256>>>(Wq, bq, nullptr, nullptr, DMODEL, DMODEL); // q=b1
    gemm_tc_kernel<0, 2, 0, -1><<<gD, 256>>>(Wk, bk, nullptr, nullptr, DMODEL, DMODEL); // k=b2
    gemm_tc_kernel<0, 3, 0, -1><<<gD, 256>>>(Wv, bv, nullptr, nullptr, DMODEL, DMODEL); // v=b3
    fa_kernel<<<dim3(SEQ / 64, BATCH * NHEAD), 256>>>();                                // ctx=b0
    gemm_tc_kernel<0, 1, 0, -2><<<gD, 256>>>(Wo, bo, nullptr, x, DMODEL, DMODEL);       // x2=b1

    // --- FFN block ---
    ln_kernel<1, 0><<<MTOK, 256>>>(nullptr, g2, be2);                                   // h=b0
    gemm_tc_kernel<0, 4, 1, -1><<<gF, 256>>>(W1, b1, nullptr, nullptr, FFDIM, DMODEL);  // act=b4
    gemm_tc_kernel<4, -1, 0, 1><<<gD, 256>>>(W2, b2, out, nullptr, DMODEL, FFDIM);      // out
}

// round 6
// speedup vs baseline: 3.1466x; 2.6190x over previous
#include <cuda_runtime.h>
#include <math.h>
#include <stdint.h>

// Problem constants
#define DMODEL 1024
#define MTOK   8192      // B*S
#define FFDIM  4096
#define NHEAD  16
#define HDIM   64
#define SEQ    1024
#define BATCH  8

// ---------------- scratch (device globals; referenced directly in kernels) ------
// b0: h (LN out) then ctx        b1: q then x2        b2: k        b3: v
// b4: FFN intermediate
__device__ float g_b0[MTOK * DMODEL];
__device__ float g_b1[MTOK * DMODEL];
__device__ float g_b2[MTOK * DMODEL];
__device__ float g_b3[MTOK * DMODEL];
__device__ float g_b4[MTOK * FFDIM];

template <int ID> __device__ __forceinline__ float* buf() {
    if constexpr (ID == 0) return g_b0;
    else if constexpr (ID == 1) return g_b1;
    else if constexpr (ID == 2) return g_b2;
    else if constexpr (ID == 3) return g_b3;
    else return g_b4;
}

// ---------------- tf32 mma helpers ----------------------------------------------
__device__ __forceinline__ uint32_t f2tf32(float x) {
    uint32_t r;
    asm("cvt.rna.tf32.f32 %0, %1;" : "=r"(r) : "f"(x));
    return r;
}

__device__ __forceinline__ void mma_tf32(float* d, const uint32_t* a, const uint32_t* b) {
    asm volatile(
        "mma.sync.aligned.m16n8k8.row.col.f32.tf32.tf32.f32 "
        "{%0,%1,%2,%3}, {%4,%5,%6,%7}, {%8,%9}, {%0,%1,%2,%3};"
        : "+f"(d[0]), "+f"(d[1]), "+f"(d[2]), "+f"(d[3])
        : "r"(a[0]), "r"(a[1]), "r"(a[2]), "r"(a[3]), "r"(b[0]), "r"(b[1]));
}

// ---------------- LayerNorm: one block per row (1024 cols, 256 thr x 4) ----------
template <int SRCID, int DSTID>
__global__ __launch_bounds__(256) void ln_kernel(const float* __restrict__ xext,
                                                 const float* __restrict__ g,
                                                 const float* __restrict__ be) {
    const float* src = (SRCID < 0) ? xext : buf<(SRCID < 0) ? 0 : SRCID>();
    float* dst = buf<DSTID>();
    __shared__ float s1[256], s2[256];
    const int row = blockIdx.x;
    const int tid = threadIdx.x;
    const float4 v = ((const float4*)(src + (size_t)row * DMODEL))[tid];
    float sum = v.x + v.y + v.z + v.w;
    float sq  = v.x*v.x + v.y*v.y + v.z*v.z + v.w*v.w;
    s1[tid] = sum; s2[tid] = sq;
    __syncthreads();
    for (int s = 128; s > 0; s >>= 1) {
        if (tid < s) { s1[tid] += s1[tid + s]; s2[tid] += s2[tid + s]; }
        __syncthreads();
    }
    const float mean = s1[0] * (1.0f / DMODEL);
    const float var  = s2[0] * (1.0f / DMODEL) - mean * mean;
    const float rs   = rsqrtf(var + 1e-5f);
    const float4 gv = ((const float4*)g)[tid];
    const float4 bv = ((const float4*)be)[tid];
    float4 o;
    o.x = (v.x - mean) * rs * gv.x + bv.x;
    o.y = (v.y - mean) * rs * gv.y + bv.y;
    o.z = (v.z - mean) * rs * gv.z + bv.z;
    o.w = (v.w - mean) * rs * gv.w + bv.w;
    ((float4*)(dst + (size_t)row * DMODEL))[tid] = o;
}

// ---------------- Dense GEMM on tensor cores (tf32), double-buffered -------------
// C = A[M,K] @ W[K,N] + bias (+GELU) (+residual).
// 128x128 block tile, BK=16, 256 threads = 8 warps (2m x 4n), warp tile 64x32.
template <int SRCID, int DSTID, int ACT, int RES>
__global__ __launch_bounds__(256) void gemm_tc_kernel(const float* __restrict__ W,
                                                      const float* __restrict__ bias,
                                                      float* __restrict__ extC,
                                                      const float* __restrict__ extRes,
                                                      int N, int K) {
    const float* A = buf<SRCID>();
    float* C = (DSTID < 0) ? extC : buf<(DSTID < 0) ? 0 : DSTID>();
    const float* R = (RES == -1) ? nullptr
                   : (RES == -2) ? extRes : buf<(RES < 0) ? 0 : RES>();

    __shared__ uint32_t As[2][128 * 20];
    __shared__ uint32_t Bs[2][16 * 136];

    const int tid  = threadIdx.x;
    const int lane = tid & 31;
    const int wid  = tid >> 5;
    const int mw0  = (wid >> 2) * 64;
    const int nw0  = (wid & 3) * 32;
    const int lr   = lane >> 2;
    const int lc   = lane & 3;
    const int rowBase = blockIdx.y * 128;
    const int colBase = blockIdx.x * 128;

    // staging indices
    const int ar0 = tid >> 2;              // 0..63 (second half +64)
    const int ac0 = (tid & 3) << 2;
    const int br0 = tid >> 5;              // 0..7  (second half +8)
    const int bc0 = (tid & 31) << 2;

    const float* Aptr0 = A + (size_t)(rowBase + ar0) * K + ac0;
    const float* Aptr1 = A + (size_t)(rowBase + ar0 + 64) * K + ac0;
    const float* Bptr0 = W + (size_t)br0 * N + colBase + bc0;
    const float* Bptr1 = W + (size_t)(br0 + 8) * N + colBase + bc0;

    float acc[4][4][4];
#pragma unroll
    for (int i = 0; i < 4; i++)
#pragma unroll
        for (int j = 0; j < 4; j++)
#pragma unroll
            for (int c = 0; c < 4; c++) acc[i][j][c] = 0.0f;

    const int nkt = K >> 4;

    // stage tile 0
    {
        const float4 a0 = *(const float4*)Aptr0;
        const float4 a1 = *(const float4*)Aptr1;
        const float4 b0 = *(const float4*)Bptr0;
        const float4 b1 = *(const float4*)Bptr1;
        uint4 u;
        u.x = f2tf32(a0.x); u.y = f2tf32(a0.y); u.z = f2tf32(a0.z); u.w = f2tf32(a0.w);
        *(uint4*)&As[0][ar0 * 20 + ac0] = u;
        u.x = f2tf32(a1.x); u.y = f2tf32(a1.y); u.z = f2tf32(a1.z); u.w = f2tf32(a1.w);
        *(uint4*)&As[0][(ar0 + 64) * 20 + ac0] = u;
        u.x = f2tf32(b0.x); u.y = f2tf32(b0.y); u.z = f2tf32(b0.z); u.w = f2tf32(b0.w);
        *(uint4*)&Bs[0][br0 * 136 + bc0] = u;
        u.x = f2tf32(b1.x); u.y = f2tf32(b1.y); u.z = f2tf32(b1.z); u.w = f2tf32(b1.w);
        *(uint4*)&Bs[0][(br0 + 8) * 136 + bc0] = u;
    }
    __syncthreads();

    for (int kt = 0; kt < nkt; kt++) {
        const int cur = kt & 1;
        float4 na0, na1, nb0, nb1;
        const bool more = (kt + 1 < nkt);
        if (more) {
            const int off = (kt + 1) << 4;
            na0 = *(const float4*)(Aptr0 + off);
            na1 = *(const float4*)(Aptr1 + off);
            nb0 = *(const float4*)(Bptr0 + (size_t)off * N);
            nb1 = *(const float4*)(Bptr1 + (size_t)off * N);
        }

        const uint32_t* Ac = As[cur];
        const uint32_t* Bc = Bs[cur];
#pragma unroll
        for (int sub = 0; sub < 16; sub += 8) {
            uint32_t a[4][4];
#pragma unroll
            for (int i = 0; i < 4; i++) {
                const uint32_t* p = Ac + (mw0 + i * 16 + lr) * 20 + sub + lc;
                a[i][0] = p[0];
                a[i][1] = p[8 * 20];
                a[i][2] = p[4];
                a[i][3] = p[8 * 20 + 4];
            }
#pragma unroll
            for (int j = 0; j < 4; j++) {
                const uint32_t* p = Bc + (sub + lc) * 136 + nw0 + j * 8 + lr;
                uint32_t bfr[2];
                bfr[0] = p[0];
                bfr[1] = p[4 * 136];
#pragma unroll
                for (int i = 0; i < 4; i++) mma_tf32(acc[i][j], a[i], bfr);
            }
        }

        if (more) {
            const int nxt = cur ^ 1;
            uint4 u;
            u.x = f2tf32(na0.x); u.y = f2tf32(na0.y); u.z = f2tf32(na0.z); u.w = f2tf32(na0.w);
            *(uint4*)&As[nxt][ar0 * 20 + ac0] = u;
            u.x = f2tf32(na1.x); u.y = f2tf32(na1.y); u.z = f2tf32(na1.z); u.w = f2tf32(na1.w);
            *(uint4*)&As[nxt][(ar0 + 64) * 20 + ac0] = u;
            u.x = f2tf32(nb0.x); u.y = f2tf32(nb0.y); u.z = f2tf32(nb0.z); u.w = f2tf32(nb0.w);
            *(uint4*)&Bs[nxt][br0 * 136 + bc0] = u;
            u.x = f2tf32(nb1.x); u.y = f2tf32(nb1.y); u.z = f2tf32(nb1.z); u.w = f2tf32(nb1.w);
            *(uint4*)&Bs[nxt][(br0 + 8) * 136 + bc0] = u;
        }
        __syncthreads();
    }

    // epilogue: bias (+GELU) (+residual), float2 stores
#pragma unroll
    for (int i = 0; i < 4; i++) {
        const int r0 = rowBase + mw0 + i * 16 + lr;
#pragma unroll
        for (int j = 0; j < 4; j++) {
            const int c0 = colBase + nw0 + j * 8 + 2 * lc;
            const float b0v = bias[c0], b1v = bias[c0 + 1];
            float v00 = acc[i][j][0] + b0v;
            float v01 = acc[i][j][1] + b1v;
            float v10 = acc[i][j][2] + b0v;
            float v11 = acc[i][j][3] + b1v;
            if (ACT == 1) {
                v00 = 0.5f * v00 * (1.0f + erff(v00 * 0.70710678118654752f));
                v01 = 0.5f * v01 * (1.0f + erff(v01 * 0.70710678118654752f));
                v10 = 0.5f * v10 * (1.0f + erff(v10 * 0.70710678118654752f));
                v11 = 0.5f * v11 * (1.0f + erff(v11 * 0.70710678118654752f));
            }
            if (R != nullptr) {
                const float2 r0v = *(const float2*)(R + (size_t)r0 * N + c0);
                const float2 r1v = *(const float2*)(R + (size_t)(r0 + 8) * N + c0);
                v00 += r0v.x; v01 += r0v.y;
                v10 += r1v.x; v11 += r1v.y;
            }
            float2 o0; o0.x = v00; o0.y = v01;
            float2 o1; o1.x = v10; o1.y = v11;
            *(float2*)(C + (size_t)r0 * N + c0) = o0;
            *(float2*)(C + (size_t)(r0 + 8) * N + c0) = o1;
        }
    }
}

// ---------------- Flash attention on tensor cores (tf32 mma) ---------------------
// Grid (SEQ/64, BATCH*NHEAD), 128 threads = 4 warps; warp owns 16 q-rows.
// Q fragments persistent in registers (scale folded). Online softmax on mma
// fragments. P round-trips through smem (aliases Ks region) for D->A layout.
__global__ __launch_bounds__(128) void fa_kernel() {
    const float* q = g_b1;
    const float* k = g_b2;
    const float* v = g_b3;
    float* ctx = g_b0;

    __shared__ uint32_t Ks[64 * 68];   // [key][hd] (S phase); aliased as P [qrow][key] (PV phase)
    __shared__ uint32_t Vs[64 * 72];   // [key][hd], stride 72 => conflict-free B loads

    const int bh = blockIdx.y;
    const int b  = bh >> 4, h = bh & 15;
    const int qBase = blockIdx.x * 64;
    const int tid  = threadIdx.x;
    const int lane = tid & 31;
    const int w    = tid >> 5;
    const int lr   = lane >> 2;
    const int lc   = lane & 3;
    const int qrow = qBase + w * 16;

    const float* qb = q + (size_t)b * SEQ * DMODEL + h * HDIM;
    const float* kb = k + (size_t)b * SEQ * DMODEL + h * HDIM;
    const float* vb = v + (size_t)b * SEQ * DMODEL + h * HDIM;

    // persistent Q fragments, pre-scaled by 1/sqrt(HD)=0.125
    uint32_t aq[8][4];
#pragma unroll
    for (int s = 0; s < 8; s++) {
        const float* p0 = qb + (size_t)(qrow + lr) * DMODEL + s * 8 + lc;
        const float* p1 = qb + (size_t)(qrow + lr + 8) * DMODEL + s * 8 + lc;
        aq[s][0] = f2tf32(p0[0] * 0.125f);
        aq[s][1] = f2tf32(p1[0] * 0.125f);
        aq[s][2] = f2tf32(p0[4] * 0.125f);
        aq[s][3] = f2tf32(p1[4] * 0.125f);
    }

    float m0 = -INFINITY, m1 = -INFINITY, l0 = 0.0f, l1 = 0.0f;
    float oacc[8][4];
#pragma unroll
    for (int j = 0; j < 8; j++)
#pragma unroll
        for (int c = 0; c < 4; c++) oacc[j][c] = 0.0f;

    for (int kt = 0; kt < SEQ / 64; kt++) {
        __syncthreads();   // previous PV reads done before overwrite
        const float* kbt = kb + (size_t)kt * 64 * DMODEL;
        const float* vbt = vb + (size_t)kt * 64 * DMODEL;
#pragma unroll
        for (int t = 0; t < 8; t++) {
            const int i = t * 128 + tid;          // 0..1023
            const int r = i >> 4, c = (i & 15) << 2;
            const float4 kv = *(const float4*)(kbt + (size_t)r * DMODEL + c);
            Ks[r * 68 + c + 0] = f2tf32(kv.x);
            Ks[r * 68 + c + 1] = f2tf32(kv.y);
            Ks[r * 68 + c + 2] = f2tf32(kv.z);
            Ks[r * 68 + c + 3] = f2tf32(kv.w);
            const float4 vv = *(const float4*)(vbt + (size_t)r * DMODEL + c);
            Vs[r * 72 + c + 0] = f2tf32(vv.x);
            Vs[r * 72 + c + 1] = f2tf32(vv.y);
            Vs[r * 72 + c + 2] = f2tf32(vv.z);
            Vs[r * 72 + c + 3] = f2tf32(vv.w);
        }
        __syncthreads();

        // S = Q @ K^T  (already scaled)
        float sacc[8][4];
#pragma unroll
        for (int j = 0; j < 8; j++)
#pragma unroll
            for (int c = 0; c < 4; c++) sacc[j][c] = 0.0f;
#pragma unroll
        for (int j = 0; j < 8; j++) {
#pragma unroll
            for (int s = 0; s < 8; s++) {
                uint32_t bfr[2];
                const uint32_t* p = Ks + (j * 8 + lr) * 68 + s * 8 + lc;
                bfr[0] = p[0];
                bfr[1] = p[4];
                mma_tf32(sacc[j], aq[s], bfr);
            }
        }

        // online softmax on fragments: rows lr (d0,d1) and lr+8 (d2,d3)
        float t0 = -INFINITY, t1 = -INFINITY;
#pragma unroll
        for (int j = 0; j < 8; j++) {
            t0 = fmaxf(t0, fmaxf(sacc[j][0], sacc[j][1]));
            t1 = fmaxf(t1, fmaxf(sacc[j][2], sacc[j][3]));
        }
        t0 = fmaxf(t0, __shfl_xor_sync(0xffffffffu, t0, 1));
        t0 = fmaxf(t0, __shfl_xor_sync(0xffffffffu, t0, 2));
        t1 = fmaxf(t1, __shfl_xor_sync(0xffffffffu, t1, 1));
        t1 = fmaxf(t1, __shfl_xor_sync(0xffffffffu, t1, 2));
        const float nm0 = fmaxf(m0, t0);
        const float nm1 = fmaxf(m1, t1);
        const float al0 = __expf(m0 - nm0);
        const float al1 = __expf(m1 - nm1);
        m0 = nm0; m1 = nm1;
        float s0 = 0.0f, s1 = 0.0f;
#pragma unroll
        for (int j = 0; j < 8; j++) {
            sacc[j][0] = __expf(sacc[j][0] - m0);
            sacc[j][1] = __expf(sacc[j][1] - m0);
            sacc[j][2] = __expf(sacc[j][2] - m1);
            sacc[j][3] = __expf(sacc[j][3] - m1);
            s0 += sacc[j][0] + sacc[j][1];
            s1 += sacc[j][2] + sacc[j][3];
        }
        s0 += __shfl_xor_sync(0xffffffffu, s0, 1);
        s0 += __shfl_xor_sync(0xffffffffu, s0, 2);
        s1 += __shfl_xor_sync(0xffffffffu, s1, 1);
        s1 += __shfl_xor_sync(0xffffffffu, s1, 2);
        l0 = l0 * al0 + s0;
        l1 = l1 * al1 + s1;
#pragma unroll
        for (int j = 0; j < 8; j++) {
            oacc[j][0] *= al0; oacc[j][1] *= al0;
            oacc[j][2] *= al1; oacc[j][3] *= al1;
        }

        // write P into Ks region (aliased) — all warps must finish reading Ks first
        __syncthreads();
        const int prow0 = (w * 16 + lr) * 68;
        const int prow1 = prow0 + 8 * 68;
#pragma unroll
        for (int j = 0; j < 8; j++) {
            Ks[prow0 + j * 8 + 2 * lc]     = f2tf32(sacc[j][0]);
            Ks[prow0 + j * 8 + 2 * lc + 1] = f2tf32(sacc[j][1]);
            Ks[prow1 + j * 8 + 2 * lc]     = f2tf32(sacc[j][2]);
            Ks[prow1 + j * 8 + 2 * lc + 1] = f2tf32(sacc[j][3]);
        }
        __syncwarp();   // P rows are warp-private

        // O += P @ V
#pragma unroll
        for (int s = 0; s < 8; s++) {
            uint32_t ap[4];
            const uint32_t* pp = Ks + (w * 16 + lr) * 68 + s * 8 + lc;
            ap[0] = pp[0];
            ap[1] = pp[8 * 68];
            ap[2] = pp[4];
            ap[3] = pp[8 * 68 + 4];
#pragma unroll
            for (int j = 0; j < 8; j++) {
                uint32_t bfr[2];
                const uint32_t* pv = Vs + (s * 8 + lc) * 72 + j * 8 + lr;
                bfr[0] = pv[0];
                bfr[1] = pv[4 * 72];
                mma_tf32(oacc[j], ap, bfr);
            }
        }
    }

    // epilogue: normalize and store ctx[b, q, h, :]
    const float inv0 = 1.0f / l0;
    const float inv1 = 1.0f / l1;
    float* crow0 = ctx + (size_t)(b * SEQ + qrow + lr) * DMODEL + h * HDIM;
    float* crow1 = ctx + (size_t)(b * SEQ + qrow + lr + 8) * DMODEL + h * HDIM;
#pragma unroll
    for (int j = 0; j < 8; j++) {
        float2 o0; o0.x = oacc[j][0] * inv0; o0.y = oacc[j][1] * inv0;
        float2 o1; o1.x = oacc[j][2] * inv1; o1.y = oacc[j][3] * inv1;
        *(float2*)(crow0 + j * 8 + 2 * lc) = o0;
        *(float2*)(crow1 + j * 8 + 2 * lc) = o1;
    }
}

// ---------------- launcher: kernel launches ONLY ---------------------------------
extern "C" void kernel_launch(void* const* d_in, const int* in_sizes, int n_in,
                              void* d_out, int out_size) {
    const float* x   = (const float*)d_in[0];
    const float* Wq  = (const float*)d_in[1];
    const float* bq  = (const float*)d_in[2];
    const float* Wk  = (const float*)d_in[3];
    const float* bk  = (const float*)d_in[4];
    const float* Wv  = (const float*)d_in[5];
    const float* bv  = (const float*)d_in[6];
    const float* Wo  = (const float*)d_in[7];
    const float* bo  = (const float*)d_in[8];
    const float* W1  = (const float*)d_in[9];
    const float* b1  = (const float*)d_in[10];
    const float* W2  = (const float*)d_in[11];
    const float* b2  = (const float*)d_in[12];
    const float* g1  = (const float*)d_in[13];
    const float* be1 = (const float*)d_in[14];
    const float* g2  = (const float*)d_in[15];
    const float* be2 = (const float*)d_in[16];
    float* out = (float*)d_out;

    const dim3 gD(DMODEL / 128, MTOK / 128);   // 8 x 64
    const dim3 gF(FFDIM / 128, MTOK / 128);    // 32 x 64

    // --- attention block ---
    ln_kernel<-1, 0><<<MTOK, 256>>>(x, g1, be1);                                        // h=b0
    gemm_tc_kernel<0, 1, 0, -1><<<gD, 256>>>(Wq, bq, nullptr, nullptr, DMODEL, DMODEL); // q=b1
    gemm_tc_kernel<0, 2, 0, -1><<<gD, 256>>>(Wk, bk, nullptr, nullptr, DMODEL, DMODEL); // k=b2
    gemm_tc_kernel<0, 3, 0, -1><<<gD, 256>>>(Wv, bv, nullptr, nullptr, DMODEL, DMODEL); // v=b3
    fa_kernel<<<dim3(SEQ / 64, BATCH * NHEAD), 128>>>();                                // ctx=b0
    gemm_tc_kernel<0, 1, 0, -2><<<gD, 256>>>(Wo, bo, nullptr, x, DMODEL, DMODEL);       // x2=b1

    // --- FFN block ---
    ln_kernel<1, 0><<<MTOK, 256>>>(nullptr, g2, be2);                                   // h=b0
    gemm_tc_kernel<0, 4, 1, -1><<<gF, 256>>>(W1, b1, nullptr, nullptr, FFDIM, DMODEL);  // act=b4
    gemm_tc_kernel<4, -1, 0, 1><<<gD, 256>>>(W2, b2, out, nullptr, DMODEL, FFDIM);      // out
}

// round 8
// speedup vs baseline: 3.3704x; 1.0711x over previous
#include <cuda_runtime.h>
#include <math.h>
#include <stdint.h>

// Problem constants
#define DMODEL 1024
#define MTOK   8192      // B*S
#define FFDIM  4096
#define NHEAD  16
#define HDIM   64
#define SEQ    1024
#define BATCH  8

// ---------------- scratch (device globals; referenced directly in kernels) ------
__device__ float g_b0[MTOK * DMODEL];
__device__ float g_b1[MTOK * DMODEL];
__device__ float g_b2[MTOK * DMODEL];
__device__ float g_b3[MTOK * DMODEL];
__device__ float g_b4[MTOK * FFDIM];

template <int ID> __device__ __forceinline__ float* buf() {
    if constexpr (ID == 0) return g_b0;
    else if constexpr (ID == 1) return g_b1;
    else if constexpr (ID == 2) return g_b2;
    else if constexpr (ID == 3) return g_b3;
    else return g_b4;
}

// ---------------- PTX helpers ----------------------------------------------------
__device__ __forceinline__ uint32_t f2tf32(float x) {
    uint32_t r;
    asm("cvt.rna.tf32.f32 %0, %1;" : "=r"(r) : "f"(x));
    return r;
}

__device__ __forceinline__ void mma_tf32(float* d, const uint32_t* a, const uint32_t* b) {
    asm volatile(
        "mma.sync.aligned.m16n8k8.row.col.f32.tf32.tf32.f32 "
        "{%0,%1,%2,%3}, {%4,%5,%6,%7}, {%8,%9}, {%0,%1,%2,%3};"
        : "+f"(d[0]), "+f"(d[1]), "+f"(d[2]), "+f"(d[3])
        : "r"(a[0]), "r"(a[1]), "r"(a[2]), "r"(a[3]), "r"(b[0]), "r"(b[1]));
}

__device__ __forceinline__ uint32_t smem_u32(const void* p) {
    uint32_t a;
    asm("{ .reg .u64 t; cvta.to.shared.u64 t, %1; cvt.u32.u64 %0, t; }" : "=r"(a) : "l"(p));
    return a;
}

#define LDMATRIX_X4(r0, r1, r2, r3, addr) \
    asm volatile("ldmatrix.sync.aligned.m8n8.x4.shared.b16 {%0,%1,%2,%3}, [%4];" \
        : "=r"(r0), "=r"(r1), "=r"(r2), "=r"(r3) : "r"(addr))

// ---------------- LayerNorm: one block per row (1024 cols, 256 thr x 4) ----------
template <int SRCID, int DSTID>
__global__ __launch_bounds__(256) void ln_kernel(const float* __restrict__ xext,
                                                 const float* __restrict__ g,
                                                 const float* __restrict__ be) {
    const float* src = (SRCID < 0) ? xext : buf<(SRCID < 0) ? 0 : SRCID>();
    float* dst = buf<DSTID>();
    __shared__ float s1[256], s2[256];
    const int row = blockIdx.x;
    const int tid = threadIdx.x;
    const float4 v = ((const float4*)(src + (size_t)row * DMODEL))[tid];
    float sum = v.x + v.y + v.z + v.w;
    float sq  = v.x*v.x + v.y*v.y + v.z*v.z + v.w*v.w;
    s1[tid] = sum; s2[tid] = sq;
    __syncthreads();
    for (int s = 128; s > 0; s >>= 1) {
        if (tid < s) { s1[tid] += s1[tid + s]; s2[tid] += s2[tid + s]; }
        __syncthreads();
    }
    const float mean = s1[0] * (1.0f / DMODEL);
    const float var  = s2[0] * (1.0f / DMODEL) - mean * mean;
    const float rs   = rsqrtf(var + 1e-5f);
    const float4 gv = ((const float4*)g)[tid];
    const float4 bv = ((const float4*)be)[tid];
    float4 o;
    o.x = (v.x - mean) * rs * gv.x + bv.x;
    o.y = (v.y - mean) * rs * gv.y + bv.y;
    o.z = (v.z - mean) * rs * gv.z + bv.z;
    o.w = (v.w - mean) * rs * gv.w + bv.w;
    ((float4*)(dst + (size_t)row * DMODEL))[tid] = o;
}

// ---------------- Dense GEMM on tensor cores (tf32 mma.sync + ldmatrix) ----------
// C = A[M,K] @ W[K,N] + bias (+GELU) (+residual).
// 128x128 block tile, BK=16, 256 threads = 8 warps (2m x 4n), warp tile 64x32.
// As: row-major [128][20] (ldmatrix-friendly, conflict-free).
// Bs: n-major [128][16] with XOR chunk swizzle (c ^= (n>>1)&3) -> conflict-free
//     v4 stores and ldmatrix loads; fragments via non-transposed ldmatrix.
template <int SRCID, int DSTID, int ACT, int RES>
__global__ __launch_bounds__(256) void gemm_tc_kernel(const float* __restrict__ W,
                                                      const float* __restrict__ bias,
                                                      float* __restrict__ extC,
                                                      const float* __restrict__ extRes,
                                                      int N, int K) {
    const float* A = buf<SRCID>();
    float* C = (DSTID < 0) ? extC : buf<(DSTID < 0) ? 0 : DSTID>();
    const float* R = (RES == -1) ? nullptr
                   : (RES == -2) ? extRes : buf<(RES < 0) ? 0 : RES>();

    __shared__ uint32_t As[2][128 * 20];
    __shared__ uint32_t Bs[2][128 * 16];

    const int tid  = threadIdx.x;
    const int lane = tid & 31;
    const int wid  = tid >> 5;
    const int mw0  = (wid >> 2) * 64;
    const int nw0  = (wid & 3) * 32;
    const int rowBase = blockIdx.y * 128;
    const int colBase = blockIdx.x * 128;

    // A staging indices
    const int ar0 = tid >> 2;              // 0..63 (second half +64)
    const int ac0 = (tid & 3) << 2;
    const float* Ap0 = A + (size_t)(rowBase + ar0) * K + ac0;
    const float* Ap1 = A + (size_t)(rowBase + ar0 + 64) * K + ac0;

    // B staging indices: warp w covers n = (w&3)*32+lane, k-quads kq0, kq0+1
    const int nS  = ((wid & 3) << 5) + lane;
    const int kq0 = (wid >> 2) << 1;
    const float* Bp = W + colBase + nS;

    float acc[4][4][4];
#pragma unroll
    for (int i = 0; i < 4; i++)
#pragma unroll
        for (int j = 0; j < 4; j++)
#pragma unroll
            for (int c = 0; c < 4; c++) acc[i][j][c] = 0.0f;

    // swizzled byte offsets for B staging stores (two quads)
    const uint32_t bso0 = nS * 64 + ((((uint32_t)kq0)     ^ ((nS >> 1) & 3)) << 4);
    const uint32_t bso1 = nS * 64 + ((((uint32_t)kq0 + 1) ^ ((nS >> 1) & 3)) << 4);

    auto loadg = [&](int c, float4& a0, float4& a1, float* nb) {
        const int k0 = c << 4;
        a0 = *(const float4*)(Ap0 + k0);
        a1 = *(const float4*)(Ap1 + k0);
#pragma unroll
        for (int t = 0; t < 2; t++) {
            const int kb = k0 + (kq0 + t) * 4;
#pragma unroll
            for (int i = 0; i < 4; i++) nb[t * 4 + i] = Bp[(size_t)(kb + i) * N];
        }
    };

    auto stage = [&](int s, const float4& a0, const float4& a1, const float* nb) {
        uint4 u;
        u.x = f2tf32(a0.x); u.y = f2tf32(a0.y); u.z = f2tf32(a0.z); u.w = f2tf32(a0.w);
        *(uint4*)&As[s][ar0 * 20 + ac0] = u;
        u.x = f2tf32(a1.x); u.y = f2tf32(a1.y); u.z = f2tf32(a1.z); u.w = f2tf32(a1.w);
        *(uint4*)&As[s][(ar0 + 64) * 20 + ac0] = u;
        uint4 b0;
        b0.x = f2tf32(nb[0]); b0.y = f2tf32(nb[1]); b0.z = f2tf32(nb[2]); b0.w = f2tf32(nb[3]);
        *(uint4*)((char*)Bs[s] + bso0) = b0;
        uint4 b1;
        b1.x = f2tf32(nb[4]); b1.y = f2tf32(nb[5]); b1.z = f2tf32(nb[6]); b1.w = f2tf32(nb[7]);
        *(uint4*)((char*)Bs[s] + bso1) = b1;
    };

    float4 ca0, ca1;
    float cnb[8];
    loadg(0, ca0, ca1, cnb);
    stage(0, ca0, ca1, cnb);
    __syncthreads();

    const int nkt = K >> 4;
    for (int kt = 0; kt < nkt; kt++) {
        const int cur = kt & 1;
        float4 pa0, pa1;
        float pnb[8];
        const bool more = (kt + 1 < nkt);
        if (more) loadg(kt + 1, pa0, pa1, pnb);

        const uint32_t abase = smem_u32(As[cur]);
        const uint32_t bbase = smem_u32(Bs[cur]);
#pragma unroll
        for (int sub = 0; sub < 16; sub += 8) {
            uint32_t a[4][4];
#pragma unroll
            for (int i = 0; i < 4; i++) {
                const uint32_t addr = abase +
                    ((mw0 + i * 16 + (lane & 15)) * 20 + sub + ((lane >> 4) << 2)) * 4;
                LDMATRIX_X4(a[i][0], a[i][1], a[i][2], a[i][3], addr);
            }
            uint32_t bb[8];
#pragma unroll
            for (int jp = 0; jp < 2; jp++) {
                const int n = nw0 + (jp * 2 + (lane >> 4)) * 8 + (lane & 7);
                const uint32_t chunk = (uint32_t)(sub >> 2) + ((lane >> 3) & 1);
                const uint32_t addr = bbase + n * 64 + ((chunk ^ ((n >> 1) & 3)) << 4);
                LDMATRIX_X4(bb[jp * 4], bb[jp * 4 + 1], bb[jp * 4 + 2], bb[jp * 4 + 3], addr);
            }
#pragma unroll
            for (int j = 0; j < 4; j++)
#pragma unroll
                for (int i = 0; i < 4; i++)
                    mma_tf32(acc[i][j], a[i], &bb[j * 2]);
        }

        if (more) stage(cur ^ 1, pa0, pa1, pnb);
        __syncthreads();
    }

    // epilogue: bias (+GELU) (+residual), float2 stores
    const int lr = lane >> 2;
    const int lc = lane & 3;
#pragma unroll
    for (int i = 0; i < 4; i++) {
        const int r0 = rowBase + mw0 + i * 16 + lr;
#pragma unroll
        for (int j = 0; j < 4; j++) {
            const int c0 = colBase + nw0 + j * 8 + 2 * lc;
            const float b0v = bias[c0], b1v = bias[c0 + 1];
            float v00 = acc[i][j][0] + b0v;
            float v01 = acc[i][j][1] + b1v;
            float v10 = acc[i][j][2] + b0v;
            float v11 = acc[i][j][3] + b1v;
            if (ACT == 1) {
                v00 = 0.5f * v00 * (1.0f + erff(v00 * 0.70710678118654752f));
                v01 = 0.5f * v01 * (1.0f + erff(v01 * 0.70710678118654752f));
                v10 = 0.5f * v10 * (1.0f + erff(v10 * 0.70710678118654752f));
                v11 = 0.5f * v11 * (1.0f + erff(v11 * 0.70710678118654752f));
            }
            if (R != nullptr) {
                const float2 r0v = *(const float2*)(R + (size_t)r0 * N + c0);
                const float2 r1v = *(const float2*)(R + (size_t)(r0 + 8) * N + c0);
                v00 += r0v.x; v01 += r0v.y;
                v10 += r1v.x; v11 += r1v.y;
            }
            float2 o0; o0.x = v00; o0.y = v01;
            float2 o1; o1.x = v10; o1.y = v11;
            *(float2*)(C + (size_t)r0 * N + c0) = o0;
            *(float2*)(C + (size_t)(r0 + 8) * N + c0) = o1;
        }
    }
}

// ---------------- Flash attention on tensor cores (tf32 mma.sync + ldmatrix) -----
// Grid (SEQ/64, BATCH*NHEAD), 128 threads = 4 warps; warp owns 16 q-rows.
// Q fragments persistent in registers (scale folded). Online softmax on mma
// fragments. P round-trips through smem (aliases Ks region) for D->A layout.
__global__ __launch_bounds__(128) void fa_kernel() {
    const float* q = g_b1;
    const float* k = g_b2;
    const float* v = g_b3;
    float* ctx = g_b0;

    __shared__ uint32_t Ks[64 * 68];   // [key][hd]; row stride 272B (16B-aligned)
    __shared__ uint32_t Vs[64 * 72];   // [key][hd]

    const int bh = blockIdx.y;
    const int b  = bh >> 4, h = bh & 15;
    const int qBase = blockIdx.x * 64;
    const int tid  = threadIdx.x;
    const int lane = tid & 31;
    const int w    = tid >> 5;
    const int lr   = lane >> 2;
    const int lc   = lane & 3;
    const int qrow = qBase + w * 16;
    const uint32_t ksbase = smem_u32(Ks);

    const float* qb = q + (size_t)b * SEQ * DMODEL + h * HDIM;
    const float* kb = k + (size_t)b * SEQ * DMODEL + h * HDIM;
    const float* vb = v + (size_t)b * SEQ * DMODEL + h * HDIM;

    // persistent Q fragments, pre-scaled by 1/sqrt(HD)=0.125
    uint32_t aq[8][4];
#pragma unroll
    for (int s = 0; s < 8; s++) {
        const float* p0 = qb + (size_t)(qrow + lr) * DMODEL + s * 8 + lc;
        const float* p1 = qb + (size_t)(qrow + lr + 8) * DMODEL + s * 8 + lc;
        aq[s][0] = f2tf32(p0[0] * 0.125f);
        aq[s][1] = f2tf32(p1[0] * 0.125f);
        aq[s][2] = f2tf32(p0[4] * 0.125f);
        aq[s][3] = f2tf32(p1[4] * 0.125f);
    }

    float m0 = -INFINITY, m1 = -INFINITY, l0 = 0.0f, l1 = 0.0f;
    float oacc[8][4];
#pragma unroll
    for (int j = 0; j < 8; j++)
#pragma unroll
        for (int c = 0; c < 4; c++) oacc[j][c] = 0.0f;

    for (int kt = 0; kt < SEQ / 64; kt++) {
        __syncthreads();
        const float* kbt = kb + (size_t)kt * 64 * DMODEL;
        const float* vbt = vb + (size_t)kt * 64 * DMODEL;
#pragma unroll
        for (int t = 0; t < 8; t++) {
            const int i = t * 128 + tid;
            const int r = i >> 4, c = (i & 15) << 2;
            const float4 kv = *(const float4*)(kbt + (size_t)r * DMODEL + c);
            Ks[r * 68 + c + 0] = f2tf32(kv.x);
            Ks[r * 68 + c + 1] = f2tf32(kv.y);
            Ks[r * 68 + c + 2] = f2tf32(kv.z);
            Ks[r * 68 + c + 3] = f2tf32(kv.w);
            const float4 vv = *(const float4*)(vbt + (size_t)r * DMODEL + c);
            Vs[r * 72 + c + 0] = f2tf32(vv.x);
            Vs[r * 72 + c + 1] = f2tf32(vv.y);
            Vs[r * 72 + c + 2] = f2tf32(vv.z);
            Vs[r * 72 + c + 3] = f2tf32(vv.w);
        }
        __syncthreads();

        // S = Q @ K^T  (already scaled); K fragments via ldmatrix
        float sacc[8][4];
#pragma unroll
        for (int j = 0; j < 8; j++)
#pragma unroll
            for (int c = 0; c < 4; c++) sacc[j][c] = 0.0f;
#pragma unroll
        for (int j = 0; j < 8; j++) {
            uint32_t bk[16];
#pragma unroll
            for (int sp = 0; sp < 4; sp++) {
                const uint32_t addr = ksbase + (j * 8 + (lane & 7)) * 272
                                    + (4 * sp + (lane >> 3)) * 16;
                LDMATRIX_X4(bk[sp * 4], bk[sp * 4 + 1], bk[sp * 4 + 2], bk[sp * 4 + 3], addr);
            }
#pragma unroll
            for (int s = 0; s < 8; s++)
                mma_tf32(sacc[j], aq[s], &bk[s * 2]);
        }

        // online softmax on fragments: rows lr (d0,d1) and lr+8 (d2,d3)
        float t0 = -INFINITY, t1 = -INFINITY;
#pragma unroll
        for (int j = 0; j < 8; j++) {
            t0 = fmaxf(t0, fmaxf(sacc[j][0], sacc[j][1]));
            t1 = fmaxf(t1, fmaxf(sacc[j][2], sacc[j][3]));
        }
        t0 = fmaxf(t0, __shfl_xor_sync(0xffffffffu, t0, 1));
        t0 = fmaxf(t0, __shfl_xor_sync(0xffffffffu, t0, 2));
        t1 = fmaxf(t1, __shfl_xor_sync(0xffffffffu, t1, 1));
        t1 = fmaxf(t1, __shfl_xor_sync(0xffffffffu, t1, 2));
        const float nm0 = fmaxf(m0, t0);
        const float nm1 = fmaxf(m1, t1);
        const float al0 = __expf(m0 - nm0);
        const float al1 = __expf(m1 - nm1);
        m0 = nm0; m1 = nm1;
        float s0 = 0.0f, s1 = 0.0f;
#pragma unroll
        for (int j = 0; j < 8; j++) {
            sacc[j][0] = __expf(sacc[j][0] - m0);
            sacc[j][1] = __expf(sacc[j][1] - m0);
            sacc[j][2] = __expf(sacc[j][2] - m1);
            sacc[j][3] = __expf(sacc[j][3] - m1);
            s0 += sacc[j][0] + sacc[j][1];
            s1 += sacc[j][2] + sacc[j][3];
        }
        s0 += __shfl_xor_sync(0xffffffffu, s0, 1);
        s0 += __shfl_xor_sync(0xffffffffu, s0, 2);
        s1 += __shfl_xor_sync(0xffffffffu, s1, 1);
        s1 += __shfl_xor_sync(0xffffffffu, s1, 2);
        l0 = l0 * al0 + s0;
        l1 = l1 * al1 + s1;
#pragma unroll
        for (int j = 0; j < 8; j++) {
            oacc[j][0] *= al0; oacc[j][1] *= al0;
            oacc[j][2] *= al1; oacc[j][3] *= al1;
        }

        // write P into Ks region (aliased) — all warps must finish reading Ks first
        __syncthreads();
        const int prow0 = (w * 16 + lr) * 68;
        const int prow1 = prow0 + 8 * 68;
#pragma unroll
        for (int j = 0; j < 8; j++) {
            Ks[prow0 + j * 8 + 2 * lc]     = f2tf32(sacc[j][0]);
            Ks[prow0 + j * 8 + 2 * lc + 1] = f2tf32(sacc[j][1]);
            Ks[prow1 + j * 8 + 2 * lc]     = f2tf32(sacc[j][2]);
            Ks[prow1 + j * 8 + 2 * lc + 1] = f2tf32(sacc[j][3]);
        }
        __syncwarp();   // P rows are warp-private

        // O += P @ V ; P fragments via ldmatrix, V fragments scalar
#pragma unroll
        for (int s = 0; s < 8; s++) {
            uint32_t ap[4];
            const uint32_t addr = ksbase + (w * 16 + (lane & 15)) * 272
                                + (2 * s + (lane >> 4)) * 16;
            LDMATRIX_X4(ap[0], ap[1], ap[2], ap[3], addr);
#pragma unroll
            for (int j = 0; j < 8; j++) {
                uint32_t bfr[2];
                const uint32_t* pv = Vs + (s * 8 + lc) * 72 + j * 8 + lr;
                bfr[0] = pv[0];
                bfr[1] = pv[4 * 72];
                mma_tf32(oacc[j], ap, bfr);
            }
        }
    }

    // epilogue: normalize and store ctx[b, q, h, :]
    const float inv0 = 1.0f / l0;
    const float inv1 = 1.0f / l1;
    float* crow0 = ctx + (size_t)(b * SEQ + qrow + lr) * DMODEL + h * HDIM;
    float* crow1 = ctx + (size_t)(b * SEQ + qrow + lr + 8) * DMODEL + h * HDIM;
#pragma unroll
    for (int j = 0; j < 8; j++) {
        float2 o0; o0.x = oacc[j][0] * inv0; o0.y = oacc[j][1] * inv0;
        float2 o1; o1.x = oacc[j][2] * inv1; o1.y = oacc[j][3] * inv1;
        *(float2*)(crow0 + j * 8 + 2 * lc) = o0;
        *(float2*)(crow1 + j * 8 + 2 * lc) = o1;
    }
}

// ---------------- launcher: kernel launches ONLY ---------------------------------
extern "C" void kernel_launch(void* const* d_in, const int* in_sizes, int n_in,
                              void* d_out, int out_size) {
    const float* x   = (const float*)d_in[0];
    const float* Wq  = (const float*)d_in[1];
    const float* bq  = (const float*)d_in[2];
    const float* Wk  = (const float*)d_in[3];
    const float* bk  = (const float*)d_in[4];
    const float* Wv  = (const float*)d_in[5];
    const float* bv  = (const float*)d_in[6];
    const float* Wo  = (const float*)d_in[7];
    const float* bo  = (const float*)d_in[8];
    const float* W1  = (const float*)d_in[9];
    const float* b1  = (const float*)d_in[10];
    const float* W2  = (const float*)d_in[11];
    const float* b2  = (const float*)d_in[12];
    const float* g1  = (const float*)d_in[13];
    const float* be1 = (const float*)d_in[14];
    const float* g2  = (const float*)d_in[15];
    const float* be2 = (const float*)d_in[16];
    float* out = (float*)d_out;

    const dim3 gD(DMODEL / 128, MTOK / 128);   // 8 x 64
    const dim3 gF(FFDIM / 128, MTOK / 128);    // 32 x 64

    // --- attention block ---
    ln_kernel<-1, 0><<<MTOK, 256>>>(x, g1, be1);                                        // h=b0
    gemm_tc_kernel<0, 1, 0, -1><<<gD, 256>>>(Wq, bq, nullptr, nullptr, DMODEL, DMODEL); // q=b1
    gemm_tc_kernel<0, 2, 0, -1><<<gD, 256>>>(Wk, bk, nullptr, nullptr, DMODEL, DMODEL); // k=b2
    gemm_tc_kernel<0, 3, 0, -1><<<gD, 256>>>(Wv, bv, nullptr, nullptr, DMODEL, DMODEL); // v=b3
    fa_kernel<<<dim3(SEQ / 64, BATCH * NHEAD), 128>>>();                                // ctx=b0
    gemm_tc_kernel<0, 1, 0, -2><<<gD, 256>>>(Wo, bo, nullptr, x, DMODEL, DMODEL);       // x2=b1

    // --- FFN block ---
    ln_kernel<1, 0><<<MTOK, 256>>>(nullptr, g2, be2);                                   // h=b0
    gemm_tc_kernel<0, 4, 1, -1><<<gF, 256>>>(W1, b1, nullptr, nullptr, FFDIM, DMODEL);  // act=b4
    gemm_tc_kernel<4, -1, 0, 1><<<gD, 256>>>(W2, b2, out, nullptr, DMODEL, FFDIM);      // out
}

// round 9
// speedup vs baseline: 3.6881x; 1.0943x over previous
#include <cuda_runtime.h>
#include <math.h>
#include <stdint.h>

// Problem constants
#define DMODEL 1024
#define MTOK   8192      // B*S
#define FFDIM  4096
#define NHEAD  16
#define HDIM   64
#define SEQ    1024
#define BATCH  8

#define STAGE_BYTES 18944            // A: 128x20 f32 (10240B) + B: 16x136 f32 (8704B)
#define GEMM_DSMEM  (3 * STAGE_BYTES)

// ---------------- scratch (device globals; referenced directly in kernels) ------
__device__ float g_b0[MTOK * DMODEL];
__device__ float g_b1[MTOK * DMODEL];
__device__ float g_b2[MTOK * DMODEL];
__device__ float g_b3[MTOK * DMODEL];
__device__ float g_b4[MTOK * FFDIM];

template <int ID> __device__ __forceinline__ float* buf() {
    if constexpr (ID == 0) return g_b0;
    else if constexpr (ID == 1) return g_b1;
    else if constexpr (ID == 2) return g_b2;
    else if constexpr (ID == 3) return g_b3;
    else return g_b4;
}

// ---------------- PTX helpers ----------------------------------------------------
__device__ __forceinline__ uint32_t f2tf32(float x) {
    uint32_t r;
    asm("cvt.rna.tf32.f32 %0, %1;" : "=r"(r) : "f"(x));
    return r;
}
__device__ __forceinline__ float roundtf(float x) {
    return __uint_as_float(f2tf32(x));
}

__device__ __forceinline__ void mma_tf32(float* d, const uint32_t* a, const uint32_t* b) {
    asm volatile(
        "mma.sync.aligned.m16n8k8.row.col.f32.tf32.tf32.f32 "
        "{%0,%1,%2,%3}, {%4,%5,%6,%7}, {%8,%9}, {%0,%1,%2,%3};"
        : "+f"(d[0]), "+f"(d[1]), "+f"(d[2]), "+f"(d[3])
        : "r"(a[0]), "r"(a[1]), "r"(a[2]), "r"(a[3]), "r"(b[0]), "r"(b[1]));
}

__device__ __forceinline__ uint32_t smem_u32(const void* p) {
    uint32_t a;
    asm("{ .reg .u64 t; cvta.to.shared.u64 t, %1; cvt.u32.u64 %0, t; }" : "=r"(a) : "l"(p));
    return a;
}

__device__ __forceinline__ void cpa16(uint32_t dst, const float* src) {
    asm volatile("cp.async.cg.shared.global [%0], [%1], 16;" :: "r"(dst), "l"(src));
}
#define CP_COMMIT() asm volatile("cp.async.commit_group;" ::: "memory")
#define CP_WAIT1()  asm volatile("cp.async.wait_group 1;" ::: "memory")

#define LDMATRIX_X4(r0, r1, r2, r3, addr) \
    asm volatile("ldmatrix.sync.aligned.m8n8.x4.shared.b16 {%0,%1,%2,%3}, [%4];" \
        : "=r"(r0), "=r"(r1), "=r"(r2), "=r"(r3) : "r"(addr))

// ---------------- LayerNorm: one block per row; stores RNA-tf32-rounded output ---
template <int SRCID, int DSTID>
__global__ __launch_bounds__(256) void ln_kernel(const float* __restrict__ xext,
                                                 const float* __restrict__ g,
                                                 const float* __restrict__ be) {
    const float* src = (SRCID < 0) ? xext : buf<(SRCID < 0) ? 0 : SRCID>();
    float* dst = buf<DSTID>();
    __shared__ float s1[256], s2[256];
    const int row = blockIdx.x;
    const int tid = threadIdx.x;
    const float4 v = ((const float4*)(src + (size_t)row * DMODEL))[tid];
    float sum = v.x + v.y + v.z + v.w;
    float sq  = v.x*v.x + v.y*v.y + v.z*v.z + v.w*v.w;
    s1[tid] = sum; s2[tid] = sq;
    __syncthreads();
    for (int s = 128; s > 0; s >>= 1) {
        if (tid < s) { s1[tid] += s1[tid + s]; s2[tid] += s2[tid + s]; }
        __syncthreads();
    }
    const float mean = s1[0] * (1.0f / DMODEL);
    const float var  = s2[0] * (1.0f / DMODEL) - mean * mean;
    const float rs   = rsqrtf(var + 1e-5f);
    const float4 gv = ((const float4*)g)[tid];
    const float4 bv = ((const float4*)be)[tid];
    float4 o;
    o.x = roundtf((v.x - mean) * rs * gv.x + bv.x);
    o.y = roundtf((v.y - mean) * rs * gv.y + bv.y);
    o.z = roundtf((v.z - mean) * rs * gv.z + bv.z);
    o.w = roundtf((v.w - mean) * rs * gv.w + bv.w);
    ((float4*)(dst + (size_t)row * DMODEL))[tid] = o;
}

// ---------------- Dense GEMM: tf32 mma.sync + cp.async 3-stage pipeline ----------
// C = A[M,K] @ W[K,N] + bias (+GELU) (+residual). 128x128 tile, BK=16, 8 warps.
// A operand is PRE-ROUNDED tf32 (producers round) -> ldmatrix feeds mma directly.
// B staged raw K-major [16][136], fragments via 2x LDS.32 + cvt.rna (conflict-free).
// DSTMODE: 0 = extC, 1..4 = buffer id, 5 = QKV (blockIdx.z selects W/bias/dst).
// ACT: 1 = exact GELU (output also RNA-rounded; feeds FFN2's A).
// RES: -1 none, -2 external residual, else buffer id.
template <int SRCID, int DSTMODE, int ACT, int RES>
__global__ __launch_bounds__(256) void gemm_cp_kernel(
    const float* __restrict__ Wa, const float* __restrict__ Wb, const float* __restrict__ Wc,
    const float* __restrict__ ba, const float* __restrict__ bb2, const float* __restrict__ bc,
    float* __restrict__ extC, const float* __restrict__ extRes, int N, int K) {
    extern __shared__ __align__(16) char dsm[];

    const float* A = buf<SRCID>();
    const int z = (DSTMODE == 5) ? blockIdx.z : 0;
    const float* W    = (DSTMODE == 5) ? (z == 0 ? Wa : (z == 1 ? Wb : Wc)) : Wa;
    const float* bias = (DSTMODE == 5) ? (z == 0 ? ba : (z == 1 ? bb2 : bc)) : ba;
    float* C = (DSTMODE == 0) ? extC
             : (DSTMODE == 5) ? (z == 0 ? g_b1 : (z == 1 ? g_b2 : g_b3))
             : buf<(DSTMODE >= 1 && DSTMODE <= 4) ? DSTMODE : 1>();
    const float* R = (RES == -1) ? nullptr
                   : (RES == -2) ? extRes : buf<(RES < 0) ? 0 : RES>();

    const int tid  = threadIdx.x;
    const int lane = tid & 31;
    const int wid  = tid >> 5;
    const int mw0  = (wid >> 2) * 64;
    const int nw0  = (wid & 3) * 32;
    const int rowBase = blockIdx.y * 128;
    const int colBase = blockIdx.x * 128;
    const uint32_t dsmb = smem_u32(dsm);

    // staging indices
    const int arow = tid >> 2;             // 0..63 (second +64)
    const int acol = tid & 3;              // 16B chunk within 64B row
    const int brow = tid >> 5;             // 0..7  (second +8)
    const int bcol = tid & 31;             // 16B chunk within 512B row
    const float* Asrc0 = A + (size_t)(rowBase + arow) * K + acol * 4;
    const float* Asrc1 = Asrc0 + (size_t)64 * K;
    const float* Bsrc0 = W + (size_t)brow * N + colBase + bcol * 4;
    const float* Bsrc1 = Bsrc0 + (size_t)8 * N;
    const uint32_t adst0 = arow * 80 + acol * 16;
    const uint32_t adst1 = (arow + 64) * 80 + acol * 16;
    const uint32_t bdst0 = 10240 + brow * 544 + bcol * 16;
    const uint32_t bdst1 = 10240 + (brow + 8) * 544 + bcol * 16;

    float acc[4][4][4];
#pragma unroll
    for (int i = 0; i < 4; i++)
#pragma unroll
        for (int j = 0; j < 4; j++)
#pragma unroll
            for (int c = 0; c < 4; c++) acc[i][j][c] = 0.0f;

    auto issue = [&](int s, int c) {
        const uint32_t st = dsmb + s * STAGE_BYTES;
        const size_t k0 = (size_t)(c << 4);
        cpa16(st + adst0, Asrc0 + k0);
        cpa16(st + adst1, Asrc1 + k0);
        cpa16(st + bdst0, Bsrc0 + k0 * N);
        cpa16(st + bdst1, Bsrc1 + k0 * N);
    };

    // prologue: 2 stages in flight
    issue(0, 0); CP_COMMIT();
    issue(1, 1); CP_COMMIT();

    const int nkt = K >> 4;
    for (int kt = 0; kt < nkt; kt++) {
        CP_WAIT1();
        __syncthreads();
        const int s = kt % 3;
        const uint32_t ab = dsmb + s * STAGE_BYTES;
        const float* Bsf = (const float*)(dsm + s * STAGE_BYTES + 10240);

#pragma unroll
        for (int sub = 0; sub < 16; sub += 8) {
            uint32_t a[4][4];
#pragma unroll
            for (int i = 0; i < 4; i++) {
                const uint32_t addr = ab + (mw0 + i * 16 + (lane & 15)) * 80
                                    + (sub + ((lane >> 4) << 2)) * 4;
                LDMATRIX_X4(a[i][0], a[i][1], a[i][2], a[i][3], addr);
            }
            const int lr = lane >> 2;
            const int lc = lane & 3;
#pragma unroll
            for (int j = 0; j < 4; j++) {
                const int nn = nw0 + j * 8 + lr;
                uint32_t bfr[2];
                bfr[0] = f2tf32(Bsf[(sub + lc) * 136 + nn]);
                bfr[1] = f2tf32(Bsf[(sub + lc + 4) * 136 + nn]);
#pragma unroll
                for (int i = 0; i < 4; i++)
                    mma_tf32(acc[i][j], a[i], bfr);
            }
        }

        if (kt + 2 < nkt) issue((kt + 2) % 3, kt + 2);
        CP_COMMIT();
    }

    // epilogue: bias (+GELU [+tf32 round]) (+residual), float2 stores
    const int lr = lane >> 2;
    const int lc = lane & 3;
#pragma unroll
    for (int i = 0; i < 4; i++) {
        const int r0 = rowBase + mw0 + i * 16 + lr;
#pragma unroll
        for (int j = 0; j < 4; j++) {
            const int c0 = colBase + nw0 + j * 8 + 2 * lc;
            const float b0v = bias[c0], b1v = bias[c0 + 1];
            float v00 = acc[i][j][0] + b0v;
            float v01 = acc[i][j][1] + b1v;
            float v10 = acc[i][j][2] + b0v;
            float v11 = acc[i][j][3] + b1v;
            if (ACT == 1) {
                v00 = roundtf(0.5f * v00 * (1.0f + erff(v00 * 0.70710678118654752f)));
                v01 = roundtf(0.5f * v01 * (1.0f + erff(v01 * 0.70710678118654752f)));
                v10 = roundtf(0.5f * v10 * (1.0f + erff(v10 * 0.70710678118654752f)));
                v11 = roundtf(0.5f * v11 * (1.0f + erff(v11 * 0.70710678118654752f)));
            }
            if (R != nullptr) {
                const float2 r0v = *(const float2*)(R + (size_t)r0 * N + c0);
                const float2 r1v = *(const float2*)(R + (size_t)(r0 + 8) * N + c0);
                v00 += r0v.x; v01 += r0v.y;
                v10 += r1v.x; v11 += r1v.y;
            }
            float2 o0; o0.x = v00; o0.y = v01;
            float2 o1; o1.x = v10; o1.y = v11;
            *(float2*)(C + (size_t)r0 * N + c0) = o0;
            *(float2*)(C + (size_t)(r0 + 8) * N + c0) = o1;
        }
    }
}

// ---------------- Flash attention on tensor cores (tf32 mma.sync + ldmatrix) -----
// ctx stores are RNA-rounded (ctx feeds the Wo GEMM's A operand only).
__global__ __launch_bounds__(128) void fa_kernel() {
    const float* q = g_b1;
    const float* k = g_b2;
    const float* v = g_b3;
    float* ctx = g_b0;

    __shared__ uint32_t Ks[64 * 68];   // [key][hd]; row stride 272B
    __shared__ uint32_t Vs[64 * 72];   // [key][hd]

    const int bh = blockIdx.y;
    const int b  = bh >> 4, h = bh & 15;
    const int qBase = blockIdx.x * 64;
    const int tid  = threadIdx.x;
    const int lane = tid & 31;
    const int w    = tid >> 5;
    const int lr   = lane >> 2;
    const int lc   = lane & 3;
    const int qrow = qBase + w * 16;
    const uint32_t ksbase = smem_u32(Ks);

    const float* qb = q + (size_t)b * SEQ * DMODEL + h * HDIM;
    const float* kb = k + (size_t)b * SEQ * DMODEL + h * HDIM;
    const float* vb = v + (size_t)b * SEQ * DMODEL + h * HDIM;

    uint32_t aq[8][4];
#pragma unroll
    for (int s = 0; s < 8; s++) {
        const float* p0 = qb + (size_t)(qrow + lr) * DMODEL + s * 8 + lc;
        const float* p1 = qb + (size_t)(qrow + lr + 8) * DMODEL + s * 8 + lc;
        aq[s][0] = f2tf32(p0[0] * 0.125f);
        aq[s][1] = f2tf32(p1[0] * 0.125f);
        aq[s][2] = f2tf32(p0[4] * 0.125f);
        aq[s][3] = f2tf32(p1[4] * 0.125f);
    }

    float m0 = -INFINITY, m1 = -INFINITY, l0 = 0.0f, l1 = 0.0f;
    float oacc[8][4];
#pragma unroll
    for (int j = 0; j < 8; j++)
#pragma unroll
        for (int c = 0; c < 4; c++) oacc[j][c] = 0.0f;

    for (int kt = 0; kt < SEQ / 64; kt++) {
        __syncthreads();
        const float* kbt = kb + (size_t)kt * 64 * DMODEL;
        const float* vbt = vb + (size_t)kt * 64 * DMODEL;
#pragma unroll
        for (int t = 0; t < 8; t++) {
            const int i = t * 128 + tid;
            const int r = i >> 4, c = (i & 15) << 2;
            const float4 kv = *(const float4*)(kbt + (size_t)r * DMODEL + c);
            Ks[r * 68 + c + 0] = f2tf32(kv.x);
            Ks[r * 68 + c + 1] = f2tf32(kv.y);
            Ks[r * 68 + c + 2] = f2tf32(kv.z);
            Ks[r * 68 + c + 3] = f2tf32(kv.w);
            const float4 vv = *(const float4*)(vbt + (size_t)r * DMODEL + c);
            Vs[r * 72 + c + 0] = f2tf32(vv.x);
            Vs[r * 72 + c + 1] = f2tf32(vv.y);
            Vs[r * 72 + c + 2] = f2tf32(vv.z);
            Vs[r * 72 + c + 3] = f2tf32(vv.w);
        }
        __syncthreads();

        float sacc[8][4];
#pragma unroll
        for (int j = 0; j < 8; j++)
#pragma unroll
            for (int c = 0; c < 4; c++) sacc[j][c] = 0.0f;
#pragma unroll
        for (int j = 0; j < 8; j++) {
            uint32_t bk[16];
#pragma unroll
            for (int sp = 0; sp < 4; sp++) {
                const uint32_t addr = ksbase + (j * 8 + (lane & 7)) * 272
                                    + (4 * sp + (lane >> 3)) * 16;
                LDMATRIX_X4(bk[sp * 4], bk[sp * 4 + 1], bk[sp * 4 + 2], bk[sp * 4 + 3], addr);
            }
#pragma unroll
            for (int s = 0; s < 8; s++)
                mma_tf32(sacc[j], aq[s], &bk[s * 2]);
        }

        float t0 = -INFINITY, t1 = -INFINITY;
#pragma unroll
        for (int j = 0; j < 8; j++) {
            t0 = fmaxf(t0, fmaxf(sacc[j][0], sacc[j][1]));
            t1 = fmaxf(t1, fmaxf(sacc[j][2], sacc[j][3]));
        }
        t0 = fmaxf(t0, __shfl_xor_sync(0xffffffffu, t0, 1));
        t0 = fmaxf(t0, __shfl_xor_sync(0xffffffffu, t0, 2));
        t1 = fmaxf(t1, __shfl_xor_sync(0xffffffffu, t1, 1));
        t1 = fmaxf(t1, __shfl_xor_sync(0xffffffffu, t1, 2));
        const float nm0 = fmaxf(m0, t0);
        const float nm1 = fmaxf(m1, t1);
        const float al0 = __expf(m0 - nm0);
        const float al1 = __expf(m1 - nm1);
        m0 = nm0; m1 = nm1;
        float s0 = 0.0f, s1 = 0.0f;
#pragma unroll
        for (int j = 0; j < 8; j++) {
            sacc[j][0] = __expf(sacc[j][0] - m0);
            sacc[j][1] = __expf(sacc[j][1] - m0);
            sacc[j][2] = __expf(sacc[j][2] - m1);
            sacc[j][3] = __expf(sacc[j][3] - m1);
            s0 += sacc[j][0] + sacc[j][1];
            s1 += sacc[j][2] + sacc[j][3];
        }
        s0 += __shfl_xor_sync(0xffffffffu, s0, 1);
        s0 += __shfl_xor_sync(0xffffffffu, s0, 2);
        s1 += __shfl_xor_sync(0xffffffffu, s1, 1);
        s1 += __shfl_xor_sync(0xffffffffu, s1, 2);
        l0 = l0 * al0 + s0;
        l1 = l1 * al1 + s1;
#pragma unroll
        for (int j = 0; j < 8; j++) {
            oacc[j][0] *= al0; oacc[j][1] *= al0;
            oacc[j][2] *= al1; oacc[j][3] *= al1;
        }

        __syncthreads();
        const int prow0 = (w * 16 + lr) * 68;
        const int prow1 = prow0 + 8 * 68;
#pragma unroll
        for (int j = 0; j < 8; j++) {
            Ks[prow0 + j * 8 + 2 * lc]     = f2tf32(sacc[j][0]);
            Ks[prow0 + j * 8 + 2 * lc + 1] = f2tf32(sacc[j][1]);
            Ks[prow1 + j * 8 + 2 * lc]     = f2tf32(sacc[j][2]);
            Ks[prow1 + j * 8 + 2 * lc + 1] = f2tf32(sacc[j][3]);
        }
        __syncwarp();

#pragma unroll
        for (int s = 0; s < 8; s++) {
            uint32_t ap[4];
            const uint32_t addr = ksbase + (w * 16 + (lane & 15)) * 272
                                + (2 * s + (lane >> 4)) * 16;
            LDMATRIX_X4(ap[0], ap[1], ap[2], ap[3], addr);
#pragma unroll
            for (int j = 0; j < 8; j++) {
                uint32_t bfr[2];
                const uint32_t* pv = Vs + (s * 8 + lc) * 72 + j * 8 + lr;
                bfr[0] = pv[0];
                bfr[1] = pv[4 * 72];
                mma_tf32(oacc[j], ap, bfr);
            }
        }
    }

    const float inv0 = 1.0f / l0;
    const float inv1 = 1.0f / l1;
    float* crow0 = ctx + (size_t)(b * SEQ + qrow + lr) * DMODEL + h * HDIM;
    float* crow1 = ctx + (size_t)(b * SEQ + qrow + lr + 8) * DMODEL + h * HDIM;
#pragma unroll
    for (int j = 0; j < 8; j++) {
        float2 o0; o0.x = roundtf(oacc[j][0] * inv0); o0.y = roundtf(oacc[j][1] * inv0);
        float2 o1; o1.x = roundtf(oacc[j][2] * inv1); o1.y = roundtf(oacc[j][3] * inv1);
        *(float2*)(crow0 + j * 8 + 2 * lc) = o0;
        *(float2*)(crow1 + j * 8 + 2 * lc) = o1;
    }
}

// ---------------- launcher -------------------------------------------------------
extern "C" void kernel_launch(void* const* d_in, const int* in_sizes, int n_in,
                              void* d_out, int out_size) {
    const float* x   = (const float*)d_in[0];
    const float* Wq  = (const float*)d_in[1];
    const float* bq  = (const float*)d_in[2];
    const float* Wk  = (const float*)d_in[3];
    const float* bk  = (const float*)d_in[4];
    const float* Wv  = (const float*)d_in[5];
    const float* bv  = (const float*)d_in[6];
    const float* Wo  = (const float*)d_in[7];
    const float* bo  = (const float*)d_in[8];
    const float* W1  = (const float*)d_in[9];
    const float* b1  = (const float*)d_in[10];
    const float* W2  = (const float*)d_in[11];
    const float* b2  = (const float*)d_in[12];
    const float* g1  = (const float*)d_in[13];
    const float* be1 = (const float*)d_in[14];
    const float* g2  = (const float*)d_in[15];
    const float* be2 = (const float*)d_in[16];
    float* out = (float*)d_out;

    // allow >48KB dynamic smem for the GEMM instantiations (idempotent, capture-safe)
    cudaFuncSetAttribute(gemm_cp_kernel<0, 5, 0, -1>,
                         cudaFuncAttributeMaxDynamicSharedMemorySize, GEMM_DSMEM);
    cudaFuncSetAttribute(gemm_cp_kernel<0, 1, 0, -2>,
                         cudaFuncAttributeMaxDynamicSharedMemorySize, GEMM_DSMEM);
    cudaFuncSetAttribute(gemm_cp_kernel<0, 4, 1, -1>,
                         cudaFuncAttributeMaxDynamicSharedMemorySize, GEMM_DSMEM);
    cudaFuncSetAttribute(gemm_cp_kernel<4, 0, 0, 1>,
                         cudaFuncAttributeMaxDynamicSharedMemorySize, GEMM_DSMEM);

    const dim3 gQKV(DMODEL / 128, MTOK / 128, 3);   // fused Q/K/V
    const dim3 gD(DMODEL / 128, MTOK / 128);        // 8 x 64
    const dim3 gF(FFDIM / 128, MTOK / 128);         // 32 x 64

    // --- attention block ---
    ln_kernel<-1, 0><<<MTOK, 256>>>(x, g1, be1);                                    // h=b0 (tf32)
    gemm_cp_kernel<0, 5, 0, -1><<<gQKV, 256, GEMM_DSMEM>>>(
        Wq, Wk, Wv, bq, bk, bv, nullptr, nullptr, DMODEL, DMODEL);                  // q,k,v = b1,b2,b3
    fa_kernel<<<dim3(SEQ / 64, BATCH * NHEAD), 128>>>();                            // ctx=b0 (tf32)
    gemm_cp_kernel<0, 1, 0, -2><<<gD, 256, GEMM_DSMEM>>>(
        Wo, Wo, Wo, bo, bo, bo, nullptr, x, DMODEL, DMODEL);                        // x2=b1 (fp32)

    // --- FFN block ---
    ln_kernel<1, 0><<<MTOK, 256>>>(nullptr, g2, be2);                               // h=b0 (tf32)
    gemm_cp_kernel<0, 4, 1, -1><<<gF, 256, GEMM_DSMEM>>>(
        W1, W1, W1, b1, b1, b1, nullptr, nullptr, FFDIM, DMODEL);                   // act=b4 (tf32)
    gemm_cp_kernel<4, 0, 0, 1><<<gD, 256, GEMM_DSMEM>>>(
        W2, W2, W2, b2, b2, b2, out, nullptr, DMODEL, FFDIM);                       // out (fp32)
}

// round 10
// speedup vs baseline: 3.6894x; 1.0004x over previous
#include <cuda_runtime.h>
#include <math.h>
#include <stdint.h>

// Problem constants
#define DMODEL 1024
#define MTOK   8192      // B*S
#define FFDIM  4096
#define NHEAD  16
#define HDIM   64
#define SEQ    1024
#define BATCH  8

#define STAGE_BYTES 18944            // A: 128x20 f32 (10240B) + B: 16x136 f32 (8704B)
#define GEMM_DSMEM  (3 * STAGE_BYTES)
#define M1 (1024 * 1024)

// ---------------- scratch (device globals; referenced directly in kernels) ------
__device__ float g_b0[MTOK * DMODEL];
__device__ float g_b1[MTOK * DMODEL];
__device__ float g_b2[MTOK * DMODEL];
__device__ float g_b3[MTOK * DMODEL];
__device__ float g_b4[MTOK * FFDIM];
// pre-rounded tf32 weights: [0:Wq][1M:Wk][2M:Wv][3M:Wo][4M:W1][8M:W2]
__device__ float g_wc[12 * M1];

template <int ID> __device__ __forceinline__ float* buf() {
    if constexpr (ID == 0) return g_b0;
    else if constexpr (ID == 1) return g_b1;
    else if constexpr (ID == 2) return g_b2;
    else if constexpr (ID == 3) return g_b3;
    else return g_b4;
}

// ---------------- PTX helpers ----------------------------------------------------
__device__ __forceinline__ uint32_t f2tf32(float x) {
    uint32_t r;
    asm("cvt.rna.tf32.f32 %0, %1;" : "=r"(r) : "f"(x));
    return r;
}
__device__ __forceinline__ float roundtf(float x) {
    return __uint_as_float(f2tf32(x));
}

// fast exp on fma pipe: exp(x) = 2^(x*log2e), magic-number split + deg-5 Taylor.
// valid for x <= 0 (softmax args); rel err ~2e-6.
__device__ __forceinline__ float fexp(float x) {
    x = fmaxf(x, -80.0f);
    const float y = x * 1.4426950408889634f;
    const float t = y + 12582912.0f;           // 2^23 + 2^22 round-to-int magic
    const int   n = __float_as_int(t) - 0x4B400000;
    const float f = y - (t - 12582912.0f);     // frac in [-0.5, 0.5]
    float p =          1.3333558e-3f;
    p = fmaf(p, f, 9.6181291e-3f);
    p = fmaf(p, f, 5.5504109e-2f);
    p = fmaf(p, f, 2.4022651e-1f);
    p = fmaf(p, f, 6.9314718e-1f);
    p = fmaf(p, f, 1.0f);
    return p * __int_as_float((n + 127) << 23);
}

__device__ __forceinline__ void mma_tf32(float* d, const uint32_t* a, const uint32_t* b) {
    asm volatile(
        "mma.sync.aligned.m16n8k8.row.col.f32.tf32.tf32.f32 "
        "{%0,%1,%2,%3}, {%4,%5,%6,%7}, {%8,%9}, {%0,%1,%2,%3};"
        : "+f"(d[0]), "+f"(d[1]), "+f"(d[2]), "+f"(d[3])
        : "r"(a[0]), "r"(a[1]), "r"(a[2]), "r"(a[3]), "r"(b[0]), "r"(b[1]));
}

__device__ __forceinline__ uint32_t smem_u32(const void* p) {
    uint32_t a;
    asm("{ .reg .u64 t; cvta.to.shared.u64 t, %1; cvt.u32.u64 %0, t; }" : "=r"(a) : "l"(p));
    return a;
}

__device__ __forceinline__ void cpa16(uint32_t dst, const float* src) {
    asm volatile("cp.async.cg.shared.global [%0], [%1], 16;" :: "r"(dst), "l"(src));
}
#define CP_COMMIT() asm volatile("cp.async.commit_group;" ::: "memory")
#define CP_WAIT1()  asm volatile("cp.async.wait_group 1;" ::: "memory")

#define LDMATRIX_X4(r0, r1, r2, r3, addr) \
    asm volatile("ldmatrix.sync.aligned.m8n8.x4.shared.b16 {%0,%1,%2,%3}, [%4];" \
        : "=r"(r0), "=r"(r1), "=r"(r2), "=r"(r3) : "r"(addr))

// ---------------- weight pre-round kernel (once per launch, ~15us) ---------------
__global__ __launch_bounds__(256) void wconv_kernel(
    const float* __restrict__ Wq, const float* __restrict__ Wk,
    const float* __restrict__ Wv, const float* __restrict__ Wo,
    const float* __restrict__ W1, const float* __restrict__ W2) {
    const size_t i4 = ((size_t)blockIdx.x * 256 + threadIdx.x) * 4;
    const float* src;
    size_t base;
    if      (i4 < 1 * M1) { src = Wq; base = 0; }
    else if (i4 < 2 * M1) { src = Wk; base = 1 * M1; }
    else if (i4 < 3 * M1) { src = Wv; base = 2 * M1; }
    else if (i4 < 4 * M1) { src = Wo; base = 3 * M1; }
    else if (i4 < 8 * M1) { src = W1; base = 4 * M1; }
    else                  { src = W2; base = 8 * M1; }
    float4 v = *(const float4*)(src + (i4 - base));
    v.x = roundtf(v.x); v.y = roundtf(v.y); v.z = roundtf(v.z); v.w = roundtf(v.w);
    *(float4*)(g_wc + i4) = v;
}

// ---------------- LayerNorm: one block per row; stores RNA-tf32-rounded output ---
template <int SRCID, int DSTID>
__global__ __launch_bounds__(256) void ln_kernel(const float* __restrict__ xext,
                                                 const float* __restrict__ g,
                                                 const float* __restrict__ be) {
    const float* src = (SRCID < 0) ? xext : buf<(SRCID < 0) ? 0 : SRCID>();
    float* dst = buf<DSTID>();
    __shared__ float s1[256], s2[256];
    const int row = blockIdx.x;
    const int tid = threadIdx.x;
    const float4 v = ((const float4*)(src + (size_t)row * DMODEL))[tid];
    float sum = v.x + v.y + v.z + v.w;
    float sq  = v.x*v.x + v.y*v.y + v.z*v.z + v.w*v.w;
    s1[tid] = sum; s2[tid] = sq;
    __syncthreads();
    for (int s = 128; s > 0; s >>= 1) {
        if (tid < s) { s1[tid] += s1[tid + s]; s2[tid] += s2[tid + s]; }
        __syncthreads();
    }
    const float mean = s1[0] * (1.0f / DMODEL);
    const float var  = s2[0] * (1.0f / DMODEL) - mean * mean;
    const float rs   = rsqrtf(var + 1e-5f);
    const float4 gv = ((const float4*)g)[tid];
    const float4 bv = ((const float4*)be)[tid];
    float4 o;
    o.x = roundtf((v.x - mean) * rs * gv.x + bv.x);
    o.y = roundtf((v.y - mean) * rs * gv.y + bv.y);
    o.z = roundtf((v.z - mean) * rs * gv.z + bv.z);
    o.w = roundtf((v.w - mean) * rs * gv.w + bv.w);
    ((float4*)(dst + (size_t)row * DMODEL))[tid] = o;
}

// ---------------- Dense GEMM: tf32 mma.sync + cp.async 3-stage pipeline ----------
// C = A[M,K] @ W[K,N] + bias (+GELU) (+residual). 128x128 tile, BK=16, 8 warps.
// A pre-rounded tf32 (producers round) -> ldmatrix direct.
// W pre-rounded tf32 (wconv) -> B fragments are plain LDS.32, no in-loop cvt.
// DSTMODE: 0 = extC, 1..4 = buffer id, 5 = QKV (blockIdx.z selects w/bias/dst).
// WOFF: weight offset into g_wc in units of 1M floats (ignored for DSTMODE 5).
template <int SRCID, int DSTMODE, int ACT, int RES, int WOFF>
__global__ __launch_bounds__(256) void gemm_cp_kernel(
    const float* __restrict__ ba, const float* __restrict__ bb2, const float* __restrict__ bc,
    float* __restrict__ extC, const float* __restrict__ extRes, int N, int K) {
    extern __shared__ __align__(16) char dsm[];

    const float* A = buf<SRCID>();
    const int z = (DSTMODE == 5) ? blockIdx.z : 0;
    const float* W    = (DSTMODE == 5) ? (g_wc + (size_t)z * M1) : (g_wc + (size_t)WOFF * M1);
    const float* bias = (DSTMODE == 5) ? (z == 0 ? ba : (z == 1 ? bb2 : bc)) : ba;
    float* C = (DSTMODE == 0) ? extC
             : (DSTMODE == 5) ? (z == 0 ? g_b1 : (z == 1 ? g_b2 : g_b3))
             : buf<(DSTMODE >= 1 && DSTMODE <= 4) ? DSTMODE : 1>();
    const float* R = (RES == -1) ? nullptr
                   : (RES == -2) ? extRes : buf<(RES < 0) ? 0 : RES>();

    const int tid  = threadIdx.x;
    const int lane = tid & 31;
    const int wid  = tid >> 5;
    const int mw0  = (wid >> 2) * 64;
    const int nw0  = (wid & 3) * 32;
    const int rowBase = blockIdx.y * 128;
    const int colBase = blockIdx.x * 128;
    const uint32_t dsmb = smem_u32(dsm);

    const int arow = tid >> 2;
    const int acol = tid & 3;
    const int brow = tid >> 5;
    const int bcol = tid & 31;
    const float* Asrc0 = A + (size_t)(rowBase + arow) * K + acol * 4;
    const float* Asrc1 = Asrc0 + (size_t)64 * K;
    const float* Bsrc0 = W + (size_t)brow * N + colBase + bcol * 4;
    const float* Bsrc1 = Bsrc0 + (size_t)8 * N;
    const uint32_t adst0 = arow * 80 + acol * 16;
    const uint32_t adst1 = (arow + 64) * 80 + acol * 16;
    const uint32_t bdst0 = 10240 + brow * 544 + bcol * 16;
    const uint32_t bdst1 = 10240 + (brow + 8) * 544 + bcol * 16;

    float acc[4][4][4];
#pragma unroll
    for (int i = 0; i < 4; i++)
#pragma unroll
        for (int j = 0; j < 4; j++)
#pragma unroll
            for (int c = 0; c < 4; c++) acc[i][j][c] = 0.0f;

    auto issue = [&](int s, int c) {
        const uint32_t st = dsmb + s * STAGE_BYTES;
        const size_t k0 = (size_t)(c << 4);
        cpa16(st + adst0, Asrc0 + k0);
        cpa16(st + adst1, Asrc1 + k0);
        cpa16(st + bdst0, Bsrc0 + k0 * N);
        cpa16(st + bdst1, Bsrc1 + k0 * N);
    };

    issue(0, 0); CP_COMMIT();
    issue(1, 1); CP_COMMIT();

    const int nkt = K >> 4;
    for (int kt = 0; kt < nkt; kt++) {
        CP_WAIT1();
        __syncthreads();
        const int s = kt % 3;
        const uint32_t ab = dsmb + s * STAGE_BYTES;
        const uint32_t* Bsu = (const uint32_t*)(dsm + s * STAGE_BYTES + 10240);

#pragma unroll
        for (int sub = 0; sub < 16; sub += 8) {
            uint32_t a[4][4];
#pragma unroll
            for (int i = 0; i < 4; i++) {
                const uint32_t addr = ab + (mw0 + i * 16 + (lane & 15)) * 80
                                    + (sub + ((lane >> 4) << 2)) * 4;
                LDMATRIX_X4(a[i][0], a[i][1], a[i][2], a[i][3], addr);
            }
            const int lr = lane >> 2;
            const int lc = lane & 3;
#pragma unroll
            for (int j = 0; j < 4; j++) {
                const int nn = nw0 + j * 8 + lr;
                uint32_t bfr[2];
                bfr[0] = Bsu[(sub + lc) * 136 + nn];
                bfr[1] = Bsu[(sub + lc + 4) * 136 + nn];
#pragma unroll
                for (int i = 0; i < 4; i++)
                    mma_tf32(acc[i][j], a[i], bfr);
            }
        }

        if (kt + 2 < nkt) issue((kt + 2) % 3, kt + 2);
        CP_COMMIT();
    }

    const int lr = lane >> 2;
    const int lc = lane & 3;
#pragma unroll
    for (int i = 0; i < 4; i++) {
        const int r0 = rowBase + mw0 + i * 16 + lr;
#pragma unroll
        for (int j = 0; j < 4; j++) {
            const int c0 = colBase + nw0 + j * 8 + 2 * lc;
            const float b0v = bias[c0], b1v = bias[c0 + 1];
            float v00 = acc[i][j][0] + b0v;
            float v01 = acc[i][j][1] + b1v;
            float v10 = acc[i][j][2] + b0v;
            float v11 = acc[i][j][3] + b1v;
            if (ACT == 1) {
                v00 = roundtf(0.5f * v00 * (1.0f + erff(v00 * 0.70710678118654752f)));
                v01 = roundtf(0.5f * v01 * (1.0f + erff(v01 * 0.70710678118654752f)));
                v10 = roundtf(0.5f * v10 * (1.0f + erff(v10 * 0.70710678118654752f)));
                v11 = roundtf(0.5f * v11 * (1.0f + erff(v11 * 0.70710678118654752f)));
            }
            if (R != nullptr) {
                const float2 r0v = *(const float2*)(R + (size_t)r0 * N + c0);
                const float2 r1v = *(const float2*)(R + (size_t)(r0 + 8) * N + c0);
                v00 += r0v.x; v01 += r0v.y;
                v10 += r1v.x; v11 += r1v.y;
            }
            float2 o0; o0.x = v00; o0.y = v01;
            float2 o1; o1.x = v10; o1.y = v11;
            *(float2*)(C + (size_t)r0 * N + c0) = o0;
            *(float2*)(C + (size_t)(r0 + 8) * N + c0) = o1;
        }
    }
}

// ---------------- Flash attention (tf32 mma.sync + ldmatrix + fma-pipe exp) ------
__global__ __launch_bounds__(128) void fa_kernel() {
    const float* q = g_b1;
    const float* k = g_b2;
    const float* v = g_b3;
    float* ctx = g_b0;

    __shared__ uint32_t Ks[64 * 68];   // [key][hd]; row stride 272B
    __shared__ uint32_t Vs[64 * 72];   // [key][hd]

    const int bh = blockIdx.y;
    const int b  = bh >> 4, h = bh & 15;
    const int qBase = blockIdx.x * 64;
    const int tid  = threadIdx.x;
    const int lane = tid & 31;
    const int w    = tid >> 5;
    const int lr   = lane >> 2;
    const int lc   = lane & 3;
    const int qrow = qBase + w * 16;
    const uint32_t ksbase = smem_u32(Ks);

    const float* qb = q + (size_t)b * SEQ * DMODEL + h * HDIM;
    const float* kb = k + (size_t)b * SEQ * DMODEL + h * HDIM;
    const float* vb = v + (size_t)b * SEQ * DMODEL + h * HDIM;

    uint32_t aq[8][4];
#pragma unroll
    for (int s = 0; s < 8; s++) {
        const float* p0 = qb + (size_t)(qrow + lr) * DMODEL + s * 8 + lc;
        const float* p1 = qb + (size_t)(qrow + lr + 8) * DMODEL + s * 8 + lc;
        aq[s][0] = f2tf32(p0[0] * 0.125f);
        aq[s][1] = f2tf32(p1[0] * 0.125f);
        aq[s][2] = f2tf32(p0[4] * 0.125f);
        aq[s][3] = f2tf32(p1[4] * 0.125f);
    }

    float m0 = -INFINITY, m1 = -INFINITY, l0 = 0.0f, l1 = 0.0f;
    float oacc[8][4];
#pragma unroll
    for (int j = 0; j < 8; j++)
#pragma unroll
        for (int c = 0; c < 4; c++) oacc[j][c] = 0.0f;

    for (int kt = 0; kt < SEQ / 64; kt++) {
        __syncthreads();
        const float* kbt = kb + (size_t)kt * 64 * DMODEL;
        const float* vbt = vb + (size_t)kt * 64 * DMODEL;
#pragma unroll
        for (int t = 0; t < 8; t++) {
            const int i = t * 128 + tid;
            const int r = i >> 4, c = (i & 15) << 2;
            const float4 kv = *(const float4*)(kbt + (size_t)r * DMODEL + c);
            Ks[r * 68 + c + 0] = f2tf32(kv.x);
            Ks[r * 68 + c + 1] = f2tf32(kv.y);
            Ks[r * 68 + c + 2] = f2tf32(kv.z);
            Ks[r * 68 + c + 3] = f2tf32(kv.w);
            const float4 vv = *(const float4*)(vbt + (size_t)r * DMODEL + c);
            Vs[r * 72 + c + 0] = f2tf32(vv.x);
            Vs[r * 72 + c + 1] = f2tf32(vv.y);
            Vs[r * 72 + c + 2] = f2tf32(vv.z);
            Vs[r * 72 + c + 3] = f2tf32(vv.w);
        }
        __syncthreads();

        float sacc[8][4];
#pragma unroll
        for (int j = 0; j < 8; j++)
#pragma unroll
            for (int c = 0; c < 4; c++) sacc[j][c] = 0.0f;
#pragma unroll
        for (int j = 0; j < 8; j++) {
            uint32_t bk[16];
#pragma unroll
            for (int sp = 0; sp < 4; sp++) {
                const uint32_t addr = ksbase + (j * 8 + (lane & 7)) * 272
                                    + (4 * sp + (lane >> 3)) * 16;
                LDMATRIX_X4(bk[sp * 4], bk[sp * 4 + 1], bk[sp * 4 + 2], bk[sp * 4 + 3], addr);
            }
#pragma unroll
            for (int s = 0; s < 8; s++)
                mma_tf32(sacc[j], aq[s], &bk[s * 2]);
        }

        float t0 = -INFINITY, t1 = -INFINITY;
#pragma unroll
        for (int j = 0; j < 8; j++) {
            t0 = fmaxf(t0, fmaxf(sacc[j][0], sacc[j][1]));
            t1 = fmaxf(t1, fmaxf(sacc[j][2], sacc[j][3]));
        }
        t0 = fmaxf(t0, __shfl_xor_sync(0xffffffffu, t0, 1));
        t0 = fmaxf(t0, __shfl_xor_sync(0xffffffffu, t0, 2));
        t1 = fmaxf(t1, __shfl_xor_sync(0xffffffffu, t1, 1));
        t1 = fmaxf(t1, __shfl_xor_sync(0xffffffffu, t1, 2));
        const float nm0 = fmaxf(m0, t0);
        const float nm1 = fmaxf(m1, t1);
        const float al0 = fexp(m0 - nm0);
        const float al1 = fexp(m1 - nm1);
        m0 = nm0; m1 = nm1;
        float s0 = 0.0f, s1 = 0.0f;
#pragma unroll
        for (int j = 0; j < 8; j++) {
            sacc[j][0] = fexp(sacc[j][0] - m0);
            sacc[j][1] = fexp(sacc[j][1] - m0);
            sacc[j][2] = fexp(sacc[j][2] - m1);
            sacc[j][3] = fexp(sacc[j][3] - m1);
            s0 += sacc[j][0] + sacc[j][1];
            s1 += sacc[j][2] + sacc[j][3];
        }
        s0 += __shfl_xor_sync(0xffffffffu, s0, 1);
        s0 += __shfl_xor_sync(0xffffffffu, s0, 2);
        s1 += __shfl_xor_sync(0xffffffffu, s1, 1);
        s1 += __shfl_xor_sync(0xffffffffu, s1, 2);
        l0 = l0 * al0 + s0;
        l1 = l1 * al1 + s1;
#pragma unroll
        for (int j = 0; j < 8; j++) {
            oacc[j][0] *= al0; oacc[j][1] *= al0;
            oacc[j][2] *= al1; oacc[j][3] *= al1;
        }

        __syncthreads();
        const int prow0 = (w * 16 + lr) * 68;
        const int prow1 = prow0 + 8 * 68;
#pragma unroll
        for (int j = 0; j < 8; j++) {
            Ks[prow0 + j * 8 + 2 * lc]     = f2tf32(sacc[j][0]);
            Ks[prow0 + j * 8 + 2 * lc + 1] = f2tf32(sacc[j][1]);
            Ks[prow1 + j * 8 + 2 * lc]     = f2tf32(sacc[j][2]);
            Ks[prow1 + j * 8 + 2 * lc + 1] = f2tf32(sacc[j][3]);
        }
        __syncwarp();

#pragma unroll
        for (int s = 0; s < 8; s++) {
            uint32_t ap[4];
            const uint32_t addr = ksbase + (w * 16 + (lane & 15)) * 272
                                + (2 * s + (lane >> 4)) * 16;
            LDMATRIX_X4(ap[0], ap[1], ap[2], ap[3], addr);
#pragma unroll
            for (int j = 0; j < 8; j++) {
                uint32_t bfr[2];
                const uint32_t* pv = Vs + (s * 8 + lc) * 72 + j * 8 + lr;
                bfr[0] = pv[0];
                bfr[1] = pv[4 * 72];
                mma_tf32(oacc[j], ap, bfr);
            }
        }
    }

    const float inv0 = 1.0f / l0;
    const float inv1 = 1.0f / l1;
    float* crow0 = ctx + (size_t)(b * SEQ + qrow + lr) * DMODEL + h * HDIM;
    float* crow1 = ctx + (size_t)(b * SEQ + qrow + lr + 8) * DMODEL + h * HDIM;
#pragma unroll
    for (int j = 0; j < 8; j++) {
        float2 o0; o0.x = roundtf(oacc[j][0] * inv0); o0.y = roundtf(oacc[j][1] * inv0);
        float2 o1; o1.x = roundtf(oacc[j][2] * inv1); o1.y = roundtf(oacc[j][3] * inv1);
        *(float2*)(crow0 + j * 8 + 2 * lc) = o0;
        *(float2*)(crow1 + j * 8 + 2 * lc) = o1;
    }
}

// ---------------- launcher -------------------------------------------------------
extern "C" void kernel_launch(void* const* d_in, const int* in_sizes, int n_in,
                              void* d_out, int out_size) {
    const float* x   = (const float*)d_in[0];
    const float* Wq  = (const float*)d_in[1];
    const float* bq  = (const float*)d_in[2];
    const float* Wk  = (const float*)d_in[3];
    const float* bk  = (const float*)d_in[4];
    const float* Wv  = (const float*)d_in[5];
    const float* bv  = (const float*)d_in[6];
    const float* Wo  = (const float*)d_in[7];
    const float* bo  = (const float*)d_in[8];
    const float* W1  = (const float*)d_in[9];
    const float* b1  = (const float*)d_in[10];
    const float* W2  = (const float*)d_in[11];
    const float* b2  = (const float*)d_in[12];
    const float* g1  = (const float*)d_in[13];
    const float* be1 = (const float*)d_in[14];
    const float* g2  = (const float*)d_in[15];
    const float* be2 = (const float*)d_in[16];
    float* out = (float*)d_out;

    cudaFuncSetAttribute(gemm_cp_kernel<0, 5, 0, -1, 0>,
                         cudaFuncAttributeMaxDynamicSharedMemorySize, GEMM_DSMEM);
    cudaFuncSetAttribute(gemm_cp_kernel<0, 1, 0, -2, 3>,
                         cudaFuncAttributeMaxDynamicSharedMemorySize, GEMM_DSMEM);
    cudaFuncSetAttribute(gemm_cp_kernel<0, 4, 1, -1, 4>,
                         cudaFuncAttributeMaxDynamicSharedMemorySize, GEMM_DSMEM);
    cudaFuncSetAttribute(gemm_cp_kernel<4, 0, 0, 1, 8>,
                         cudaFuncAttributeMaxDynamicSharedMemorySize, GEMM_DSMEM);

    const dim3 gQKV(DMODEL / 128, MTOK / 128, 3);
    const dim3 gD(DMODEL / 128, MTOK / 128);
    const dim3 gF(FFDIM / 128, MTOK / 128);

    // weight pre-round (independent of LN; runs first)
    wconv_kernel<<<12 * M1 / 1024, 256>>>(Wq, Wk, Wv, Wo, W1, W2);

    // --- attention block ---
    ln_kernel<-1, 0><<<MTOK, 256>>>(x, g1, be1);                                    // h=b0 (tf32)
    gemm_cp_kernel<0, 5, 0, -1, 0><<<gQKV, 256, GEMM_DSMEM>>>(
        bq, bk, bv, nullptr, nullptr, DMODEL, DMODEL);                              // q,k,v
    fa_kernel<<<dim3(SEQ / 64, BATCH * NHEAD), 128>>>();                            // ctx=b0 (tf32)
    gemm_cp_kernel<0, 1, 0, -2, 3><<<gD, 256, GEMM_DSMEM>>>(
        bo, bo, bo, nullptr, x, DMODEL, DMODEL);                                    // x2=b1 (fp32)

    // --- FFN block ---
    ln_kernel<1, 0><<<MTOK, 256>>>(nullptr, g2, be2);                               // h=b0 (tf32)
    gemm_cp_kernel<0, 4, 1, -1, 4><<<gF, 256, GEMM_DSMEM>>>(
        b1, b1, b1, nullptr, nullptr, FFDIM, DMODEL);                               // act=b4 (tf32)
    gemm_cp_kernel<4, 0, 0, 1, 8><<<gD, 256, GEMM_DSMEM>>>(
        b2, b2, b2, out, nullptr, DMODEL, FFDIM);                                   // out (fp32)
}